// round 1
// baseline (speedup 1.0000x reference)
#include <cuda_runtime.h>
#include <cstdint>
#include <cstddef>

#define T_STEPS 16
#define B_ROWS  16384
#define D_IN    512
#define HID     512
#define OUT_N   7
#define M_TOT   (T_STEPS * B_ROWS)   /* 262144 */
#define N_CAT   1024
#define K_DIM   512

// Scratch (static device globals — no allocation at runtime).
__device__ float g_pre[(size_t)M_TOT * N_CAT];   // [T*B, 1024]: cols 0..511 = x@W_gc+b_gc, 512..1023 = x@W_d1_top+b_d1
__device__ float g_bcat[K_DIM * N_CAT];          // [512, 1024] = [W_gc | W_d1[:512]]
__device__ float g_bias[N_CAT];

// ---------------------------------------------------------------------------
// Prep: build concatenated weight matrix + bias vector
// ---------------------------------------------------------------------------
__global__ void prep_kernel(const float* __restrict__ W_gc, const float* __restrict__ b_gc,
                            const float* __restrict__ W_d1, const float* __restrict__ b_d1)
{
    int i = blockIdx.x * blockDim.x + threadIdx.x;
    if (i < K_DIM * N_CAT) {
        int k = i >> 10;
        int j = i & 1023;
        g_bcat[i] = (j < HID) ? W_gc[k * HID + j] : W_d1[k * HID + (j - HID)];
    }
    if (i < N_CAT) {
        g_bias[i] = (i < HID) ? b_gc[i] : b_d1[i - HID];
    }
}

// ---------------------------------------------------------------------------
// FP32 SIMT GEMM: C[M_TOT, 1024] = x[M_TOT, 512] @ g_bcat + g_bias
// 128x128 block tile, BK=16, 256 threads, 8x8 per-thread microtile.
// ---------------------------------------------------------------------------
#define BM 128
#define BN 128
#define BK 16
#define TM 8
#define TN 8

__global__ __launch_bounds__(256, 2) void sgemm_kernel(const float* __restrict__ A)
{
    __shared__ float As[BK][BM + 4];   // A stored transposed (k-major)
    __shared__ float Bs[BK][BN + 4];

    const int tid  = threadIdx.x;
    const int brow = blockIdx.y;       // 0..M_TOT/BM-1
    const int bcol = blockIdx.x;       // 0..N_CAT/BN-1

    const float* Ab = A + (size_t)brow * BM * K_DIM;
    const float* Bb = g_bcat + bcol * BN;

    // A tile loads: 128x16 floats = 512 float4, 2 per thread
    const int arow = tid >> 2;          // 0..63
    const int acol = (tid & 3) << 2;    // 0,4,8,12
    // B tile loads: 16x128 floats = 512 float4, 2 per thread
    const int brw  = tid >> 5;          // 0..7
    const int bcl  = (tid & 31) << 2;   // 0..124

    const int trow = (tid >> 4) * TM;   // 0..120
    const int tcol = (tid & 15) * TN;   // 0..120

    float acc[TM][TN];
    #pragma unroll
    for (int i = 0; i < TM; i++)
        #pragma unroll
        for (int j = 0; j < TN; j++) acc[i][j] = 0.f;

    for (int k0 = 0; k0 < K_DIM; k0 += BK) {
        #pragma unroll
        for (int i = 0; i < 2; i++) {
            float4 v = *(const float4*)(Ab + (size_t)(arow + 64 * i) * K_DIM + k0 + acol);
            As[acol + 0][arow + 64 * i] = v.x;
            As[acol + 1][arow + 64 * i] = v.y;
            As[acol + 2][arow + 64 * i] = v.z;
            As[acol + 3][arow + 64 * i] = v.w;
        }
        #pragma unroll
        for (int i = 0; i < 2; i++) {
            *(float4*)(&Bs[brw + 8 * i][bcl]) =
                *(const float4*)(Bb + (size_t)(k0 + brw + 8 * i) * N_CAT + bcl);
        }
        __syncthreads();

        #pragma unroll
        for (int kk = 0; kk < BK; kk++) {
            float ra[TM], rb[TN];
            #pragma unroll
            for (int i = 0; i < TM; i++) ra[i] = As[kk][trow + i];
            #pragma unroll
            for (int j = 0; j < TN; j++) rb[j] = Bs[kk][tcol + j];
            #pragma unroll
            for (int i = 0; i < TM; i++)
                #pragma unroll
                for (int j = 0; j < TN; j++)
                    acc[i][j] += ra[i] * rb[j];
        }
        __syncthreads();
    }

    float bias[TN];
    #pragma unroll
    for (int j = 0; j < TN; j++) bias[j] = g_bias[bcol * BN + tcol + j];

    float* Cb = g_pre + (size_t)(brow * BM) * N_CAT + bcol * BN;
    #pragma unroll
    for (int i = 0; i < TM; i++) {
        #pragma unroll
        for (int j = 0; j < TN; j += 4) {
            float4 v;
            v.x = acc[i][j + 0] + bias[j + 0];
            v.y = acc[i][j + 1] + bias[j + 1];
            v.z = acc[i][j + 2] + bias[j + 2];
            v.w = acc[i][j + 3] + bias[j + 3];
            *(float4*)(Cb + (size_t)(trow + i) * N_CAT + tcol + j) = v;
        }
    }
}

// ---------------------------------------------------------------------------
// Recurrence: one block (128 threads) per batch row; all 16 timesteps fused.
// Membranes m1/m2/m3 live in registers (4 neurons/thread, j = 128*q + tid).
// Spikes are exact {0,1}; spike @ W is a gather of W rows via ballot bitmasks.
// ---------------------------------------------------------------------------
__global__ __launch_bounds__(128) void recur_kernel(
    const float* __restrict__ W_pc, const float* __restrict__ b_pc,
    const float* __restrict__ W_d1, const float* __restrict__ W_d2,
    const float* __restrict__ b_d2, float* __restrict__ out)
{
    const int b    = blockIdx.x;
    const int tid  = threadIdx.x;
    const int lane = tid & 31;
    const int w    = tid >> 5;

    __shared__ unsigned gcmask[16];   // bit k of neuron index space: word m covers [32m, 32m+32)
    __shared__ unsigned pcmask[16];
    __shared__ float    sred[OUT_N * 4];

    float m1[4] = {0.f, 0.f, 0.f, 0.f};
    float m2[4] = {0.f, 0.f, 0.f, 0.f};
    float m3[4] = {0.f, 0.f, 0.f, 0.f};
    float oacc[OUT_N] = {0.f, 0.f, 0.f, 0.f, 0.f, 0.f, 0.f};

    float bpc[4];
    #pragma unroll
    for (int q = 0; q < 4; q++) bpc[q] = b_pc[128 * q + tid];

    for (int t = 0; t < T_STEPS; t++) {
        const float* pre = g_pre + ((size_t)t * B_ROWS + b) * N_CAT;

        // ---- LIF1: gc spikes (input = precomputed x@W_gc + b_gc) ----
        #pragma unroll
        for (int q = 0; q < 4; q++) {
            float v = 0.5f * (m1[q] + pre[128 * q + tid]);
            bool  s = v > 1.0f;
            m1[q]   = s ? 0.f : v;
            unsigned bal = __ballot_sync(0xffffffffu, s);
            if (lane == 0) gcmask[4 * q + w] = bal;   // word (4q+w) covers neurons [32*(4q+w), +32)
        }
        __syncthreads();

        // ---- layer2: pc_pre = gc @ W_pc + b_pc (sparse row gather) ----
        float a2[4] = {bpc[0], bpc[1], bpc[2], bpc[3]};
        #pragma unroll 1
        for (int mw = 0; mw < 16; mw++) {
            unsigned mm = gcmask[mw];
            while (mm) {
                int l = __ffs(mm) - 1;
                mm &= mm - 1;
                const float* wr = W_pc + (size_t)((mw << 5) + l) * HID;
                #pragma unroll
                for (int q = 0; q < 4; q++) a2[q] += wr[128 * q + tid];
            }
        }

        // ---- LIF2: pc spikes ----
        #pragma unroll
        for (int q = 0; q < 4; q++) {
            float v = 0.5f * (m2[q] + a2[q]);
            bool  s = v > 1.0f;
            m2[q]   = s ? 0.f : v;
            unsigned bal = __ballot_sync(0xffffffffu, s);
            if (lane == 0) pcmask[4 * q + w] = bal;
        }
        __syncthreads();

        // ---- layer3: d1_pre = (x@W_d1_top + b_d1) [precomputed] + pc @ W_d1_bottom ----
        float a3[4];
        #pragma unroll
        for (int q = 0; q < 4; q++) a3[q] = pre[HID + 128 * q + tid];
        #pragma unroll 1
        for (int mw = 0; mw < 16; mw++) {
            unsigned mm = pcmask[mw];
            while (mm) {
                int l = __ffs(mm) - 1;
                mm &= mm - 1;
                const float* wr = W_d1 + (size_t)(HID + (mw << 5) + l) * HID;
                #pragma unroll
                for (int q = 0; q < 4; q++) a3[q] += wr[128 * q + tid];
            }
        }

        // ---- LIF3: s3 spikes -> readout accumulate ----
        #pragma unroll
        for (int q = 0; q < 4; q++) {
            float v = 0.5f * (m3[q] + a3[q]);
            bool  s = v > 1.0f;
            m3[q]   = s ? 0.f : v;
            if (s) {
                const float* wr = W_d2 + (size_t)(128 * q + tid) * OUT_N;
                #pragma unroll
                for (int o = 0; o < OUT_N; o++) oacc[o] += wr[o];
            }
        }
        __syncthreads();   // protect gcmask/pcmask reuse next step
    }

    // ---- block reduction of 7 outputs ----
    #pragma unroll
    for (int o = 0; o < OUT_N; o++) {
        float v = oacc[o];
        #pragma unroll
        for (int off = 16; off; off >>= 1) v += __shfl_down_sync(0xffffffffu, v, off);
        if (lane == 0) sred[o * 4 + w] = v;
    }
    __syncthreads();
    if (tid < OUT_N) {
        float s = sred[tid * 4] + sred[tid * 4 + 1] + sred[tid * 4 + 2] + sred[tid * 4 + 3];
        out[(size_t)b * OUT_N + tid] = s * (1.0f / (float)T_STEPS) + b_d2[tid];
    }
}

// ---------------------------------------------------------------------------
extern "C" void kernel_launch(void* const* d_in, const int* in_sizes, int n_in,
                              void* d_out, int out_size)
{
    const float* x    = (const float*)d_in[0];
    const float* W_gc = (const float*)d_in[1];
    const float* b_gc = (const float*)d_in[2];
    const float* W_pc = (const float*)d_in[3];
    const float* b_pc = (const float*)d_in[4];
    const float* W_d1 = (const float*)d_in[5];
    const float* b_d1 = (const float*)d_in[6];
    const float* W_d2 = (const float*)d_in[7];
    const float* b_d2 = (const float*)d_in[8];
    float* out = (float*)d_out;
    (void)in_sizes; (void)n_in; (void)out_size;

    prep_kernel<<<(K_DIM * N_CAT + 255) / 256, 256>>>(W_gc, b_gc, W_d1, b_d1);

    dim3 grid(N_CAT / BN, M_TOT / BM);   // (8, 2048)
    sgemm_kernel<<<grid, 256>>>(x);

    recur_kernel<<<B_ROWS, 128>>>(W_pc, b_pc, W_d1, W_d2, b_d2, out);
}

// round 3
// speedup vs baseline: 2.2097x; 2.2097x over previous
#include <cuda_runtime.h>
#include <cuda_fp16.h>
#include <cstdint>
#include <cstddef>

#define T_STEPS 16
#define B_ROWS  16384
#define HID     512
#define OUT_N   7
#define M_TOT   (T_STEPS * B_ROWS)   /* 262144 */
#define N_CAT   1024
#define K_DIM   512

// ---------------------------------------------------------------------------
// Static device scratch (no runtime allocation)
// ---------------------------------------------------------------------------
__device__ float  g_pre[(size_t)M_TOT * N_CAT];     // [T*B, 1024] pre-activations
__device__ __half g_xs0[(size_t)M_TOT * K_DIM];     // x hi split
__device__ __half g_xs1[(size_t)M_TOT * K_DIM];     // x lo split
__device__ __half g_ws0[(size_t)N_CAT * K_DIM];     // (1024*W)^T hi split, [N,K]
__device__ __half g_ws1[(size_t)N_CAT * K_DIM];     // (1024*W)^T lo split
__device__ float  g_bias[N_CAT];

// ---------------------------------------------------------------------------
// Baseline-PTX helpers (valid on plain sm_103 target: cp.async + mma.sync)
// ---------------------------------------------------------------------------
__device__ __forceinline__ uint32_t smem_u32(const void* p) {
    uint32_t a;
    asm("{ .reg .u64 t; cvta.to.shared.u64 t, %1; cvt.u32.u64 %0, t; }" : "=r"(a) : "l"(p));
    return a;
}
__device__ __forceinline__ void cp16(uint32_t dst, const void* src) {
    asm volatile("cp.async.cg.shared.global [%0], [%1], 16;" :: "r"(dst), "l"(src) : "memory");
}
__device__ __forceinline__ void cp_commit() {
    asm volatile("cp.async.commit_group;" ::: "memory");
}
__device__ __forceinline__ void cp_wait0() {
    asm volatile("cp.async.wait_group 0;" ::: "memory");
}
__device__ __forceinline__ void ldsm4(uint32_t* r, uint32_t addr) {
    asm volatile("ldmatrix.sync.aligned.m8n8.x4.shared.b16 {%0,%1,%2,%3}, [%4];"
                 : "=r"(r[0]), "=r"(r[1]), "=r"(r[2]), "=r"(r[3]) : "r"(addr));
}
__device__ __forceinline__ void mma16816(float* c, const uint32_t* a, const uint32_t* b) {
    asm volatile("mma.sync.aligned.m16n8k16.row.col.f32.f16.f16.f32 "
                 "{%0,%1,%2,%3}, {%4,%5,%6,%7}, {%8,%9}, {%0,%1,%2,%3};"
                 : "+f"(c[0]), "+f"(c[1]), "+f"(c[2]), "+f"(c[3])
                 : "r"(a[0]), "r"(a[1]), "r"(a[2]), "r"(a[3]), "r"(b[0]), "r"(b[1]));
}

// ---------------------------------------------------------------------------
// Split conversions: a = hi + lo in fp16 (residual <= ~2^-22 rel)
// ---------------------------------------------------------------------------
__global__ void convert_x_kernel(const float4* __restrict__ x)
{
    size_t i = (size_t)blockIdx.x * blockDim.x + threadIdx.x;
    float4 v = x[i];
    float f[4] = {v.x, v.y, v.z, v.w};
    union { __half h[4]; uint2 u; } p0, p1;
    #pragma unroll
    for (int k = 0; k < 4; k++) {
        __half a = __float2half_rn(f[k]);
        float  r = f[k] - __half2float(a);
        p0.h[k] = a;
        p1.h[k] = __float2half_rn(r);
    }
    ((uint2*)g_xs0)[i] = p0.u;
    ((uint2*)g_xs1)[i] = p1.u;
}

__global__ void convert_w_kernel(const float* __restrict__ W_gc, const float* __restrict__ W_d1,
                                 const float* __restrict__ b_gc, const float* __restrict__ b_d1)
{
    int i = blockIdx.x * blockDim.x + threadIdx.x;   // 524288
    int n = i >> 9, k = i & 511;
    float w = (n < HID) ? W_gc[k * HID + n] : W_d1[k * HID + (n - HID)];
    w *= 1024.0f;            // exact pow2 scale; keeps lo-split out of fp16 subnormals
    __half a = __float2half_rn(w);
    float  r = w - __half2float(a);
    g_ws0[(size_t)n * K_DIM + k] = a;
    g_ws1[(size_t)n * K_DIM + k] = __float2half_rn(r);
    if (i < N_CAT) g_bias[i] = (i < HID) ? b_gc[i] : b_d1[i - HID];
}

// ---------------------------------------------------------------------------
// Split-fp16 HMMA GEMM: g_pre = ((x0+x1) @ (w0+w1)^T) * 2^-10 + bias
// 3 products: x0w0 + x0w1 + x1w0  (x1w1 term ~1e-8, dropped)
// CTA 128x128, 8 warps (2m x 4n, warp 64x32), k-chunk 32, 2-stage cp.async.
// ---------------------------------------------------------------------------
#define GM 128
#define GN 128
#define KCH 32
#define ROWB 80                        /* 32 halves + 8 pad  -> conflict-free ldsm */
#define SPL_BYTES (128 * ROWB)         /* 10240 per split-tile */
#define STAGE (4 * SPL_BYTES)          /* A0 A1 B0 B1 = 40960 */
#define GEMM_SMEM (2 * STAGE)          /* 81920 */

__global__ void __launch_bounds__(256, 2) gemm_mma_kernel()
{
    extern __shared__ char smem[];
    const uint32_t sb = smem_u32(smem);
    const int tid  = threadIdx.x;
    const int lane = tid & 31;
    const int wid  = tid >> 5;
    const int wm = (wid >> 2) * 64;             // warp m offset in tile
    const int wn = (wid & 3) * 32;              // warp n offset in tile
    const size_t m0 = (size_t)blockIdx.y * GM;
    const int    n0 = blockIdx.x * GN;

    float c[4][4][4];
    #pragma unroll
    for (int i = 0; i < 4; i++)
        #pragma unroll
        for (int j = 0; j < 4; j++)
            #pragma unroll
            for (int k = 0; k < 4; k++) c[i][j][k] = 0.f;

    auto load_stage = [&](int cc, int st) {
        uint32_t base = sb + st * STAGE;
        #pragma unroll
        for (int i = 0; i < 4; i++) {           // A: 1024 x 16B units
            int u = tid + 256 * i;
            int p = u >> 9, r = (u >> 2) & 127, j = u & 3;
            const __half* src = (p ? g_xs1 : g_xs0) + (m0 + r) * K_DIM + cc * KCH + j * 8;
            cp16(base + p * SPL_BYTES + r * ROWB + j * 16, src);
        }
        #pragma unroll
        for (int i = 0; i < 4; i++) {           // B: 1024 x 16B units
            int u = tid + 256 * i;
            int p = u >> 9, r = (u >> 2) & 127, j = u & 3;
            const __half* src = (p ? g_ws1 : g_ws0) + (size_t)(n0 + r) * K_DIM + cc * KCH + j * 8;
            cp16(base + 2 * SPL_BYTES + p * SPL_BYTES + r * ROWB + j * 16, src);
        }
        cp_commit();
    };

    auto compute_stage = [&](int st) {
        uint32_t Ab = sb + st * STAGE;
        uint32_t Bb = Ab + 2 * SPL_BYTES;
        #pragma unroll
        for (int kk = 0; kk < 2; kk++) {        // two k16 steps per 32-chunk
            uint32_t a[2][4][4];
            uint32_t b[2][4][2];
            #pragma unroll
            for (int p = 0; p < 2; p++)
                #pragma unroll
                for (int mi = 0; mi < 4; mi++) {
                    uint32_t addr = Ab + p * SPL_BYTES
                                  + (wm + 16 * mi + (lane & 15)) * ROWB
                                  + kk * 32 + (lane >> 4) * 16;
                    ldsm4(a[p][mi], addr);
                }
            #pragma unroll
            for (int p = 0; p < 2; p++)
                #pragma unroll
                for (int jj = 0; jj < 2; jj++) {
                    uint32_t nr = wn + 16 * jj + ((lane >> 4) & 1) * 8 + (lane & 7);
                    uint32_t addr = Bb + p * SPL_BYTES + nr * ROWB
                                  + kk * 32 + ((lane >> 3) & 1) * 16;
                    uint32_t r4[4];
                    ldsm4(r4, addr);
                    b[p][2 * jj][0]     = r4[0]; b[p][2 * jj][1]     = r4[1];
                    b[p][2 * jj + 1][0] = r4[2]; b[p][2 * jj + 1][1] = r4[3];
                }
            #pragma unroll
            for (int mi = 0; mi < 4; mi++)
                #pragma unroll
                for (int nj = 0; nj < 4; nj++) {
                    mma16816(c[mi][nj], a[0][mi], b[0][nj]);
                    mma16816(c[mi][nj], a[0][mi], b[1][nj]);
                    mma16816(c[mi][nj], a[1][mi], b[0][nj]);
                }
        }
    };

    load_stage(0, 0);
    #pragma unroll 1
    for (int cc = 0; cc < K_DIM / KCH; cc++) {
        cp_wait0();
        __syncthreads();
        if (cc + 1 < K_DIM / KCH) load_stage(cc + 1, (cc + 1) & 1);
        compute_stage(cc & 1);
    }

    // epilogue: scale 2^-10, add bias, store fp32
    const float sc = 1.0f / 1024.0f;
    const int g = lane >> 2, t4 = lane & 3;
    #pragma unroll
    for (int mi = 0; mi < 4; mi++) {
        #pragma unroll
        for (int nj = 0; nj < 4; nj++) {
            int col = n0 + wn + 8 * nj + t4 * 2;
            float b0 = g_bias[col], b1 = g_bias[col + 1];
            size_t row = m0 + wm + 16 * mi + g;
            float2 v0 = {c[mi][nj][0] * sc + b0, c[mi][nj][1] * sc + b1};
            *(float2*)(g_pre + row * N_CAT + col) = v0;
            float2 v1 = {c[mi][nj][2] * sc + b0, c[mi][nj][3] * sc + b1};
            *(float2*)(g_pre + (row + 8) * N_CAT + col) = v1;
        }
    }
}

// ---------------------------------------------------------------------------
// Recurrence (unchanged — spike-exact, validated round 1)
// ---------------------------------------------------------------------------
__global__ void __launch_bounds__(128) recur_kernel(
    const float* __restrict__ W_pc, const float* __restrict__ b_pc,
    const float* __restrict__ W_d1, const float* __restrict__ W_d2,
    const float* __restrict__ b_d2, float* __restrict__ out)
{
    const int b    = blockIdx.x;
    const int tid  = threadIdx.x;
    const int lane = tid & 31;
    const int w    = tid >> 5;

    __shared__ unsigned gcmask[16];
    __shared__ unsigned pcmask[16];
    __shared__ float    sred[OUT_N * 4];

    float m1[4] = {0.f, 0.f, 0.f, 0.f};
    float m2[4] = {0.f, 0.f, 0.f, 0.f};
    float m3[4] = {0.f, 0.f, 0.f, 0.f};
    float oacc[OUT_N] = {0.f, 0.f, 0.f, 0.f, 0.f, 0.f, 0.f};

    float bpc[4];
    #pragma unroll
    for (int q = 0; q < 4; q++) bpc[q] = b_pc[128 * q + tid];

    for (int t = 0; t < T_STEPS; t++) {
        const float* pre = g_pre + ((size_t)t * B_ROWS + b) * N_CAT;

        #pragma unroll
        for (int q = 0; q < 4; q++) {
            float v = 0.5f * (m1[q] + pre[128 * q + tid]);
            bool  s = v > 1.0f;
            m1[q]   = s ? 0.f : v;
            unsigned bal = __ballot_sync(0xffffffffu, s);
            if (lane == 0) gcmask[4 * q + w] = bal;
        }
        __syncthreads();

        float a2[4] = {bpc[0], bpc[1], bpc[2], bpc[3]};
        #pragma unroll 1
        for (int mw = 0; mw < 16; mw++) {
            unsigned mm = gcmask[mw];
            while (mm) {
                int l = __ffs(mm) - 1;
                mm &= mm - 1;
                const float* wr = W_pc + (size_t)((mw << 5) + l) * HID;
                #pragma unroll
                for (int q = 0; q < 4; q++) a2[q] += wr[128 * q + tid];
            }
        }

        #pragma unroll
        for (int q = 0; q < 4; q++) {
            float v = 0.5f * (m2[q] + a2[q]);
            bool  s = v > 1.0f;
            m2[q]   = s ? 0.f : v;
            unsigned bal = __ballot_sync(0xffffffffu, s);
            if (lane == 0) pcmask[4 * q + w] = bal;
        }
        __syncthreads();

        float a3[4];
        #pragma unroll
        for (int q = 0; q < 4; q++) a3[q] = pre[HID + 128 * q + tid];
        #pragma unroll 1
        for (int mw = 0; mw < 16; mw++) {
            unsigned mm = pcmask[mw];
            while (mm) {
                int l = __ffs(mm) - 1;
                mm &= mm - 1;
                const float* wr = W_d1 + (size_t)(HID + (mw << 5) + l) * HID;
                #pragma unroll
                for (int q = 0; q < 4; q++) a3[q] += wr[128 * q + tid];
            }
        }

        #pragma unroll
        for (int q = 0; q < 4; q++) {
            float v = 0.5f * (m3[q] + a3[q]);
            bool  s = v > 1.0f;
            m3[q]   = s ? 0.f : v;
            if (s) {
                const float* wr = W_d2 + (size_t)(128 * q + tid) * OUT_N;
                #pragma unroll
                for (int o = 0; o < OUT_N; o++) oacc[o] += wr[o];
            }
        }
        __syncthreads();
    }

    #pragma unroll
    for (int o = 0; o < OUT_N; o++) {
        float v = oacc[o];
        #pragma unroll
        for (int off = 16; off; off >>= 1) v += __shfl_down_sync(0xffffffffu, v, off);
        if (lane == 0) sred[o * 4 + w] = v;
    }
    __syncthreads();
    if (tid < OUT_N) {
        float s = sred[tid * 4] + sred[tid * 4 + 1] + sred[tid * 4 + 2] + sred[tid * 4 + 3];
        out[(size_t)b * OUT_N + tid] = s * (1.0f / (float)T_STEPS) + b_d2[tid];
    }
}

// ---------------------------------------------------------------------------
extern "C" void kernel_launch(void* const* d_in, const int* in_sizes, int n_in,
                              void* d_out, int out_size)
{
    const float* x    = (const float*)d_in[0];
    const float* W_gc = (const float*)d_in[1];
    const float* b_gc = (const float*)d_in[2];
    const float* W_pc = (const float*)d_in[3];
    const float* b_pc = (const float*)d_in[4];
    const float* W_d1 = (const float*)d_in[5];
    const float* b_d1 = (const float*)d_in[6];
    const float* W_d2 = (const float*)d_in[7];
    const float* b_d2 = (const float*)d_in[8];
    float* out = (float*)d_out;
    (void)in_sizes; (void)n_in; (void)out_size;

    static bool attr_set = false;
    cudaFuncSetAttribute(gemm_mma_kernel, cudaFuncAttributeMaxDynamicSharedMemorySize, GEMM_SMEM);
    (void)attr_set;

    convert_x_kernel<<<((size_t)M_TOT * K_DIM / 4) / 256, 256>>>((const float4*)x);
    convert_w_kernel<<<(N_CAT * K_DIM) / 256, 256>>>(W_gc, W_d1, b_gc, b_d1);

    dim3 grid(N_CAT / GN, M_TOT / GM);   // (8, 2048); x fastest -> A tiles shared via L2
    gemm_mma_kernel<<<grid, 256, GEMM_SMEM>>>();

    recur_kernel<<<B_ROWS, 128>>>(W_pc, b_pc, W_d1, W_d2, b_d2, out);
}

// round 4
// speedup vs baseline: 2.3905x; 1.0818x over previous
#include <cuda_runtime.h>
#include <cuda_fp16.h>
#include <cstdint>
#include <cstddef>

#define T_STEPS 16
#define B_ROWS  16384
#define HID     512
#define OUT_N   7
#define M_TOT   (T_STEPS * B_ROWS)   /* 262144 */
#define N_CAT   1024
#define K_DIM   512

// ---------------------------------------------------------------------------
// Static device scratch (no runtime allocation)
// ---------------------------------------------------------------------------
__device__ float  g_pre[(size_t)M_TOT * N_CAT];     // [T*B, 1024] pre-activations
__device__ __half g_xs0[(size_t)M_TOT * K_DIM];     // x hi split
__device__ __half g_xs1[(size_t)M_TOT * K_DIM];     // x lo split
__device__ __half g_ws0[(size_t)N_CAT * K_DIM];     // (1024*W)^T hi split, [N,K]
__device__ __half g_ws1[(size_t)N_CAT * K_DIM];     // (1024*W)^T lo split
__device__ float  g_bias[N_CAT];

// ---------------------------------------------------------------------------
// Helpers — baseline PTX (sm_80+, valid in every pass)
// ---------------------------------------------------------------------------
__device__ __forceinline__ uint32_t smem_u32(const void* p) {
    uint32_t a;
    asm("{ .reg .u64 t; cvta.to.shared.u64 t, %1; cvt.u32.u64 %0, t; }" : "=r"(a) : "l"(p));
    return a;
}
__device__ __forceinline__ void cp16(uint32_t dst, const void* src) {
    asm volatile("cp.async.cg.shared.global [%0], [%1], 16;" :: "r"(dst), "l"(src) : "memory");
}
__device__ __forceinline__ void cp_commit() {
    asm volatile("cp.async.commit_group;" ::: "memory");
}
__device__ __forceinline__ void cp_wait0() {
    asm volatile("cp.async.wait_group 0;" ::: "memory");
}
__device__ __forceinline__ void ldsm4(uint32_t* r, uint32_t addr) {
    asm volatile("ldmatrix.sync.aligned.m8n8.x4.shared.b16 {%0,%1,%2,%3}, [%4];"
                 : "=r"(r[0]), "=r"(r[1]), "=r"(r[2]), "=r"(r[3]) : "r"(addr));
}
__device__ __forceinline__ void mma16816(float* c, const uint32_t* a, const uint32_t* b) {
    asm volatile("mma.sync.aligned.m16n8k16.row.col.f32.f16.f16.f32 "
                 "{%0,%1,%2,%3}, {%4,%5,%6,%7}, {%8,%9}, {%0,%1,%2,%3};"
                 : "+f"(c[0]), "+f"(c[1]), "+f"(c[2]), "+f"(c[3])
                 : "r"(a[0]), "r"(a[1]), "r"(a[2]), "r"(a[3]), "r"(b[0]), "r"(b[1]));
}
__device__ __forceinline__ uint32_t sw128(uint32_t off) {
    return off ^ ((off >> 3) & 0x70);
}

// ---------------------------------------------------------------------------
// Helpers — sm_103a-only (only instantiated inside the feature-guarded path)
// ---------------------------------------------------------------------------
#if defined(__CUDA_ARCH_FEAT_SM103_ALL)
__device__ __forceinline__ bool elect1() {
    uint32_t p;
    asm volatile("{ .reg .pred P; elect.sync _|P, 0xFFFFFFFF; selp.b32 %0, 1, 0, P; }" : "=r"(p));
    return p != 0;
}
__device__ __forceinline__ void mbar_init(uint32_t mbar, uint32_t cnt) {
    asm volatile("mbarrier.init.shared.b64 [%0], %1;" :: "r"(mbar), "r"(cnt) : "memory");
}
__device__ __forceinline__ void mbar_wait(uint32_t mbar, uint32_t parity) {
    asm volatile(
        "{\n\t.reg .pred P;\n\t"
        "LW_%=:\n\t"
        "mbarrier.try_wait.parity.acquire.cta.shared::cta.b64 P, [%0], %1, 0x989680;\n\t"
        "@P bra.uni LD_%=;\n\t"
        "bra.uni LW_%=;\n\t"
        "LD_%=:\n\t}"
        :: "r"(mbar), "r"(parity) : "memory");
}
__device__ __forceinline__ void tmem_alloc(uint32_t dst_smem, uint32_t ncols) {
    asm volatile("tcgen05.alloc.cta_group::1.sync.aligned.shared::cta.b32 [%0], %1;"
                 :: "r"(dst_smem), "r"(ncols) : "memory");
}
__device__ __forceinline__ void tmem_dealloc(uint32_t tmem, uint32_t ncols) {
    asm volatile("tcgen05.relinquish_alloc_permit.cta_group::1.sync.aligned;" ::: "memory");
    asm volatile("tcgen05.dealloc.cta_group::1.sync.aligned.b32 %0, %1;" :: "r"(tmem), "r"(ncols));
}
__device__ __forceinline__ void mma_f16_ss(uint32_t d, uint64_t ad, uint64_t bd,
                                           uint32_t idesc, uint32_t en) {
    asm volatile(
        "{\n\t.reg .pred p;\n\t"
        "setp.ne.u32 p, %4, 0;\n\t"
        "tcgen05.mma.cta_group::1.kind::f16 [%0], %1, %2, %3, {%5, %5, %5, %5}, p;\n\t}"
        :: "r"(d), "l"(ad), "l"(bd), "r"(idesc), "r"(en), "r"(0u) : "memory");
}
__device__ __forceinline__ void mma_commit(uint32_t mbar) {
    asm volatile("tcgen05.commit.cta_group::1.mbarrier::arrive::one.shared::cluster.b64 [%0];"
                 :: "r"(mbar) : "memory");
}
__device__ __forceinline__ void fence_async_shared() {
    asm volatile("fence.proxy.async.shared::cta;" ::: "memory");
}
__device__ __forceinline__ void tcgen05_fence_after() {
    asm volatile("tcgen05.fence::after_thread_sync;" ::: "memory");
}
__device__ __forceinline__ void tmem_wait_ld() {
    asm volatile("tcgen05.wait::ld.sync.aligned;" ::: "memory");
}
#define LDTM_X32(r, addr) \
    asm volatile( \
        "tcgen05.ld.sync.aligned.32x32b.x32.b32 " \
        "{%0, %1, %2, %3, %4, %5, %6, %7, " \
        " %8, %9, %10, %11, %12, %13, %14, %15, " \
        " %16, %17, %18, %19, %20, %21, %22, %23, " \
        " %24, %25, %26, %27, %28, %29, %30, %31}, [%32];" \
        : "=r"((r)[0]),  "=r"((r)[1]),  "=r"((r)[2]),  "=r"((r)[3]), \
          "=r"((r)[4]),  "=r"((r)[5]),  "=r"((r)[6]),  "=r"((r)[7]), \
          "=r"((r)[8]),  "=r"((r)[9]),  "=r"((r)[10]), "=r"((r)[11]), \
          "=r"((r)[12]), "=r"((r)[13]), "=r"((r)[14]), "=r"((r)[15]), \
          "=r"((r)[16]), "=r"((r)[17]), "=r"((r)[18]), "=r"((r)[19]), \
          "=r"((r)[20]), "=r"((r)[21]), "=r"((r)[22]), "=r"((r)[23]), \
          "=r"((r)[24]), "=r"((r)[25]), "=r"((r)[26]), "=r"((r)[27]), \
          "=r"((r)[28]), "=r"((r)[29]), "=r"((r)[30]), "=r"((r)[31]) \
        : "r"(addr))

static constexpr uint64_t DESC_BASE_SW128 =
    (2ULL << 61) | (1ULL << 46) | (64ULL << 32) | (1ULL << 16);
__device__ __forceinline__ uint64_t mkdesc(uint32_t base) {
    return DESC_BASE_SW128 | (uint64_t)((base >> 4) & 0x3FFF);
}
#endif  // __CUDA_ARCH_FEAT_SM103_ALL

// ---------------------------------------------------------------------------
// Split conversions: a = hi + lo in fp16
// ---------------------------------------------------------------------------
__global__ void convert_x_kernel(const float4* __restrict__ x)
{
    size_t i = (size_t)blockIdx.x * blockDim.x + threadIdx.x;
    float4 v = x[i];
    float f[4] = {v.x, v.y, v.z, v.w};
    union { __half h[4]; uint2 u; } p0, p1;
    #pragma unroll
    for (int k = 0; k < 4; k++) {
        __half a = __float2half_rn(f[k]);
        float  r = f[k] - __half2float(a);
        p0.h[k] = a;
        p1.h[k] = __float2half_rn(r);
    }
    ((uint2*)g_xs0)[i] = p0.u;
    ((uint2*)g_xs1)[i] = p1.u;
}

__global__ void convert_w_kernel(const float* __restrict__ W_gc, const float* __restrict__ W_d1,
                                 const float* __restrict__ b_gc, const float* __restrict__ b_d1)
{
    int i = blockIdx.x * blockDim.x + threadIdx.x;   // 524288
    int n = i >> 9, k = i & 511;
    float w = (n < HID) ? W_gc[k * HID + n] : W_d1[k * HID + (n - HID)];
    w *= 1024.0f;            // exact pow2 scale; keeps lo-split out of fp16 subnormals
    __half a = __float2half_rn(w);
    float  r = w - __half2float(a);
    g_ws0[(size_t)n * K_DIM + k] = a;
    g_ws1[(size_t)n * K_DIM + k] = __float2half_rn(r);
    if (i < N_CAT) g_bias[i] = (i < HID) ? b_gc[i] : b_d1[i - HID];
}

// ---------------------------------------------------------------------------
// GEMM: g_pre = ((x0+x1) @ (w0+w1)^T) * 2^-10 + bias  (3 split-products)
// CTA tile 128x128. Dual path: tcgen05 on sm_103a cubin, HMMA on compute_103.
// ---------------------------------------------------------------------------
#define GM 128
#define GN 128
#define GEMM_SMEM 81920

__global__ void __launch_bounds__(256, 2) gemm_kernel()
{
    extern __shared__ char smem[];
    const int tid  = threadIdx.x;
    const int lane = tid & 31;
    const int wid  = tid >> 5;
    const size_t m0 = (size_t)blockIdx.y * GM;
    const int    n0 = blockIdx.x * GN;

#if defined(__CUDA_ARCH_FEAT_SM103_ALL)
    // ======================= tcgen05 path (sm_103a) =======================
    // smem: [align1024] A0(16K) A1(16K) B0(16K) B1(16K); ctrl/mbar static.
    __shared__ __align__(16) uint32_t s_ctrl[4];     // [0]=tmem ptr; [2..3]=mbarrier
    char* tile_ptr = (char*)(((uintptr_t)smem + 1023) & ~(uintptr_t)1023);
    const uint32_t SA   = smem_u32(tile_ptr);
    const uint32_t SB   = SA + 32768;
    const uint32_t ctrl = smem_u32(&s_ctrl[0]);
    const uint32_t mbar = smem_u32(&s_ctrl[2]);

    if (wid == 0) tmem_alloc(ctrl, 128);
    if (tid == 0) mbar_init(mbar, 1);
    __syncthreads();
    uint32_t tmem;
    asm volatile("ld.shared.b32 %0, [%1];" : "=r"(tmem) : "r"(ctrl));

    const uint32_t IDESC = (1u << 4) | ((GN / 8) << 17) | ((GM / 16) << 24);

    #pragma unroll 1
    for (int c = 0; c < K_DIM / 64; c++) {           // 8 chunks of K=64
        if (c) mbar_wait(mbar, (c - 1) & 1);         // prev chunk's MMAs done

        // stage A (2 splits x 128 rows x 128B) and B (same) via cp.async
        #pragma unroll
        for (int i = 0; i < 8; i++) {
            int u = tid + 256 * i;                   // 0..2047
            int p = u >> 10, r = u & 1023, row = r >> 3, j = r & 7;
            const __half* sa = (p ? g_xs1 : g_xs0) + (m0 + row) * K_DIM + c * 64 + j * 8;
            cp16(SA + p * 16384 + sw128(row * 128 + j * 16), sa);
            const __half* sbp = (p ? g_ws1 : g_ws0) + (size_t)(n0 + row) * K_DIM + c * 64 + j * 8;
            cp16(SB + p * 16384 + sw128(row * 128 + j * 16), sbp);
        }
        cp_commit();
        cp_wait0();
        fence_async_shared();
        __syncthreads();

        if (wid == 0 && elect1()) {
            uint64_t dA0 = mkdesc(SA), dA1 = mkdesc(SA + 16384);
            uint64_t dB0 = mkdesc(SB), dB1 = mkdesc(SB + 16384);
            #pragma unroll
            for (int ks = 0; ks < 4; ks++) {
                uint32_t en = (c == 0 && ks == 0) ? 0u : 1u;
                mma_f16_ss(tmem, dA0 + 2 * ks, dB0 + 2 * ks, IDESC, en);
                mma_f16_ss(tmem, dA0 + 2 * ks, dB1 + 2 * ks, IDESC, 1u);
                mma_f16_ss(tmem, dA1 + 2 * ks, dB0 + 2 * ks, IDESC, 1u);
            }
            mma_commit(mbar);
        }
        __syncthreads();                              // keep warps in step with MMA issue
    }

    mbar_wait(mbar, (K_DIM / 64 - 1) & 1);
    tcgen05_fence_after();

    if (wid < 4) {                                    // warp w -> rows 32w..32w+31
        size_t row = m0 + wid * 32 + lane;
        float* cp = g_pre + row * N_CAT + n0;
        const float sc = 1.0f / 1024.0f;
        #pragma unroll
        for (int cb = 0; cb < 4; cb++) {
            uint32_t r[32];
            LDTM_X32(r, tmem + cb * 32);
            tmem_wait_ld();
            #pragma unroll
            for (int j = 0; j < 32; j += 4) {
                float4 v;
                v.x = __uint_as_float(r[j + 0]) * sc + g_bias[n0 + cb * 32 + j + 0];
                v.y = __uint_as_float(r[j + 1]) * sc + g_bias[n0 + cb * 32 + j + 1];
                v.z = __uint_as_float(r[j + 2]) * sc + g_bias[n0 + cb * 32 + j + 2];
                v.w = __uint_as_float(r[j + 3]) * sc + g_bias[n0 + cb * 32 + j + 3];
                *(float4*)(cp + cb * 32 + j) = v;
            }
        }
    }
    __syncthreads();
    if (wid == 0) tmem_dealloc(tmem, 128);

#else
    // ======================= HMMA fallback (compute_103) ==================
    const uint32_t sb = smem_u32(smem);
    const int wm = (wid >> 2) * 64;
    const int wn = (wid & 3) * 32;
    #define ROWB 80
    #define SPL_BYTES (128 * ROWB)
    #define STAGE (4 * SPL_BYTES)

    float c[4][4][4];
    #pragma unroll
    for (int i = 0; i < 4; i++)
        #pragma unroll
        for (int j = 0; j < 4; j++)
            #pragma unroll
            for (int k = 0; k < 4; k++) c[i][j][k] = 0.f;

    auto load_stage = [&](int cc, int st) {
        uint32_t base = sb + st * STAGE;
        #pragma unroll
        for (int i = 0; i < 4; i++) {
            int u = tid + 256 * i;
            int p = u >> 9, r = (u >> 2) & 127, j = u & 3;
            const __half* src = (p ? g_xs1 : g_xs0) + (m0 + r) * K_DIM + cc * 32 + j * 8;
            cp16(base + p * SPL_BYTES + r * ROWB + j * 16, src);
        }
        #pragma unroll
        for (int i = 0; i < 4; i++) {
            int u = tid + 256 * i;
            int p = u >> 9, r = (u >> 2) & 127, j = u & 3;
            const __half* src = (p ? g_ws1 : g_ws0) + (size_t)(n0 + r) * K_DIM + cc * 32 + j * 8;
            cp16(base + 2 * SPL_BYTES + p * SPL_BYTES + r * ROWB + j * 16, src);
        }
        cp_commit();
    };

    auto compute_stage = [&](int st) {
        uint32_t Ab = sb + st * STAGE;
        uint32_t Bb = Ab + 2 * SPL_BYTES;
        #pragma unroll
        for (int kk = 0; kk < 2; kk++) {
            uint32_t a[2][4][4];
            uint32_t b[2][4][2];
            #pragma unroll
            for (int p = 0; p < 2; p++)
                #pragma unroll
                for (int mi = 0; mi < 4; mi++) {
                    uint32_t addr = Ab + p * SPL_BYTES
                                  + (wm + 16 * mi + (lane & 15)) * ROWB
                                  + kk * 32 + (lane >> 4) * 16;
                    ldsm4(a[p][mi], addr);
                }
            #pragma unroll
            for (int p = 0; p < 2; p++)
                #pragma unroll
                for (int jj = 0; jj < 2; jj++) {
                    uint32_t nr = wn + 16 * jj + ((lane >> 4) & 1) * 8 + (lane & 7);
                    uint32_t addr = Bb + p * SPL_BYTES + nr * ROWB
                                  + kk * 32 + ((lane >> 3) & 1) * 16;
                    uint32_t r4[4];
                    ldsm4(r4, addr);
                    b[p][2 * jj][0]     = r4[0]; b[p][2 * jj][1]     = r4[1];
                    b[p][2 * jj + 1][0] = r4[2]; b[p][2 * jj + 1][1] = r4[3];
                }
            #pragma unroll
            for (int mi = 0; mi < 4; mi++)
                #pragma unroll
                for (int nj = 0; nj < 4; nj++) {
                    mma16816(c[mi][nj], a[0][mi], b[0][nj]);
                    mma16816(c[mi][nj], a[0][mi], b[1][nj]);
                    mma16816(c[mi][nj], a[1][mi], b[0][nj]);
                }
        }
    };

    load_stage(0, 0);
    #pragma unroll 1
    for (int cc = 0; cc < K_DIM / 32; cc++) {
        cp_wait0();
        __syncthreads();
        if (cc + 1 < K_DIM / 32) load_stage(cc + 1, (cc + 1) & 1);
        compute_stage(cc & 1);
    }

    const float sc = 1.0f / 1024.0f;
    const int g = lane >> 2, t4 = lane & 3;
    #pragma unroll
    for (int mi = 0; mi < 4; mi++) {
        #pragma unroll
        for (int nj = 0; nj < 4; nj++) {
            int col = n0 + wn + 8 * nj + t4 * 2;
            float b0 = g_bias[col], b1 = g_bias[col + 1];
            size_t row = m0 + wm + 16 * mi + g;
            float2 v0 = {c[mi][nj][0] * sc + b0, c[mi][nj][1] * sc + b1};
            *(float2*)(g_pre + row * N_CAT + col) = v0;
            float2 v1 = {c[mi][nj][2] * sc + b0, c[mi][nj][3] * sc + b1};
            *(float2*)(g_pre + (row + 8) * N_CAT + col) = v1;
        }
    }
    #undef ROWB
    #undef SPL_BYTES
    #undef STAGE
#endif
}

// ---------------------------------------------------------------------------
// Recurrence: neuron j = 4*tid + q  -> all gathers are float4 (LDG.128)
// Ballot word widx = 4*q + w; bit l  <->  neuron 128*w + 4*l + q
// ---------------------------------------------------------------------------
__global__ void __launch_bounds__(128) recur_kernel(
    const float* __restrict__ W_pc, const float* __restrict__ b_pc,
    const float* __restrict__ W_d1, const float* __restrict__ W_d2,
    const float* __restrict__ b_d2, float* __restrict__ out)
{
    const int b    = blockIdx.x;
    const int tid  = threadIdx.x;
    const int lane = tid & 31;
    const int w    = tid >> 5;

    __shared__ unsigned gcmask[16];
    __shared__ unsigned pcmask[16];
    __shared__ float    sred[OUT_N * 4];

    float m1[4] = {0.f, 0.f, 0.f, 0.f};
    float m2[4] = {0.f, 0.f, 0.f, 0.f};
    float m3[4] = {0.f, 0.f, 0.f, 0.f};
    float oacc[OUT_N] = {0.f, 0.f, 0.f, 0.f, 0.f, 0.f, 0.f};

    float4 bpc4 = ((const float4*)b_pc)[tid];
    float bpc[4] = {bpc4.x, bpc4.y, bpc4.z, bpc4.w};

    for (int t = 0; t < T_STEPS; t++) {
        const float* pre = g_pre + ((size_t)t * B_ROWS + b) * N_CAT;
        float4 p4 = ((const float4*)pre)[tid];
        float pr[4] = {p4.x, p4.y, p4.z, p4.w};

        // ---- LIF1 ----
        #pragma unroll
        for (int q = 0; q < 4; q++) {
            float v = 0.5f * (m1[q] + pr[q]);
            bool  s = v > 1.0f;
            m1[q]   = s ? 0.f : v;
            unsigned bal = __ballot_sync(0xffffffffu, s);
            if (lane == 0) gcmask[4 * q + w] = bal;
        }
        __syncthreads();

        // ---- pc_pre = gc @ W_pc + b_pc (sparse float4 row gather) ----
        float a2[4] = {bpc[0], bpc[1], bpc[2], bpc[3]};
        #pragma unroll 1
        for (int mw = 0; mw < 16; mw++) {
            unsigned mm = gcmask[mw];
            int q = mw >> 2, wb = (mw & 3) << 7;
            while (mm) {
                int l = __ffs(mm) - 1;
                mm &= mm - 1;
                int row = wb + 4 * l + q;
                float4 wv = ((const float4*)(W_pc + (size_t)row * HID))[tid];
                a2[0] += wv.x; a2[1] += wv.y; a2[2] += wv.z; a2[3] += wv.w;
            }
        }

        // ---- LIF2 ----
        #pragma unroll
        for (int q = 0; q < 4; q++) {
            float v = 0.5f * (m2[q] + a2[q]);
            bool  s = v > 1.0f;
            m2[q]   = s ? 0.f : v;
            unsigned bal = __ballot_sync(0xffffffffu, s);
            if (lane == 0) pcmask[4 * q + w] = bal;
        }
        __syncthreads();

        // ---- d1_pre = precomputed x-part + pc @ W_d1_bottom ----
        float4 p4b = ((const float4*)(pre + HID))[tid];
        float a3[4] = {p4b.x, p4b.y, p4b.z, p4b.w};
        #pragma unroll 1
        for (int mw = 0; mw < 16; mw++) {
            unsigned mm = pcmask[mw];
            int q = mw >> 2, wb = (mw & 3) << 7;
            while (mm) {
                int l = __ffs(mm) - 1;
                mm &= mm - 1;
                int row = HID + wb + 4 * l + q;
                float4 wv = ((const float4*)(W_d1 + (size_t)row * HID))[tid];
                a3[0] += wv.x; a3[1] += wv.y; a3[2] += wv.z; a3[3] += wv.w;
            }
        }

        // ---- LIF3 -> readout ----
        #pragma unroll
        for (int q = 0; q < 4; q++) {
            float v = 0.5f * (m3[q] + a3[q]);
            bool  s = v > 1.0f;
            m3[q]   = s ? 0.f : v;
            if (s) {
                const float* wr = W_d2 + (size_t)(4 * tid + q) * OUT_N;
                #pragma unroll
                for (int o = 0; o < OUT_N; o++) oacc[o] += wr[o];
            }
        }
        __syncthreads();
    }

    #pragma unroll
    for (int o = 0; o < OUT_N; o++) {
        float v = oacc[o];
        #pragma unroll
        for (int off = 16; off; off >>= 1) v += __shfl_down_sync(0xffffffffu, v, off);
        if (lane == 0) sred[o * 4 + w] = v;
    }
    __syncthreads();
    if (tid < OUT_N) {
        float s = sred[tid * 4] + sred[tid * 4 + 1] + sred[tid * 4 + 2] + sred[tid * 4 + 3];
        out[(size_t)b * OUT_N + tid] = s * (1.0f / (float)T_STEPS) + b_d2[tid];
    }
}

// ---------------------------------------------------------------------------
extern "C" void kernel_launch(void* const* d_in, const int* in_sizes, int n_in,
                              void* d_out, int out_size)
{
    const float* x    = (const float*)d_in[0];
    const float* W_gc = (const float*)d_in[1];
    const float* b_gc = (const float*)d_in[2];
    const float* W_pc = (const float*)d_in[3];
    const float* b_pc = (const float*)d_in[4];
    const float* W_d1 = (const float*)d_in[5];
    const float* b_d1 = (const float*)d_in[6];
    const float* W_d2 = (const float*)d_in[7];
    const float* b_d2 = (const float*)d_in[8];
    float* out = (float*)d_out;
    (void)in_sizes; (void)n_in; (void)out_size;

    cudaFuncSetAttribute(gemm_kernel, cudaFuncAttributeMaxDynamicSharedMemorySize, GEMM_SMEM);

    convert_x_kernel<<<((size_t)M_TOT * K_DIM / 4) / 256, 256>>>((const float4*)x);
    convert_w_kernel<<<(N_CAT * K_DIM) / 256, 256>>>(W_gc, W_d1, b_gc, b_d1);

    dim3 grid(N_CAT / GN, M_TOT / GM);   // (8, 2048); x fastest -> A tiles reuse L2
    gemm_kernel<<<grid, 256, GEMM_SMEM>>>();

    recur_kernel<<<B_ROWS, 128>>>(W_pc, b_pc, W_d1, W_d2, b_d2, out);
}

// round 5
// speedup vs baseline: 3.3604x; 1.4057x over previous
#include <cuda_runtime.h>
#include <cuda_fp16.h>
#include <cstdint>
#include <cstddef>

#define T_STEPS 16
#define B_ROWS  16384
#define HID     512
#define OUT_N   7
#define M_TOT   (T_STEPS * B_ROWS)   /* 262144 */
#define N_CAT   1024
#define K_DIM   512

// ---------------------------------------------------------------------------
// Static device scratch (no runtime allocation)
// ---------------------------------------------------------------------------
__device__ float  g_pre[(size_t)M_TOT * N_CAT];     // [T*B, 1024] pre-activations
__device__ __half g_xs0[(size_t)M_TOT * K_DIM];     // x hi split
__device__ __half g_xs1[(size_t)M_TOT * K_DIM];     // x lo split
__device__ __half g_ws0[(size_t)N_CAT * K_DIM];     // (1024*W)^T hi split, [N,K]
__device__ __half g_ws1[(size_t)N_CAT * K_DIM];     // (1024*W)^T lo split
__device__ float  g_bias[N_CAT];

// ---------------------------------------------------------------------------
// Helpers — baseline PTX (sm_80+, valid in every compilation pass)
// ---------------------------------------------------------------------------
__device__ __forceinline__ uint32_t smem_u32(const void* p) {
    uint32_t a;
    asm("{ .reg .u64 t; cvta.to.shared.u64 t, %1; cvt.u32.u64 %0, t; }" : "=r"(a) : "l"(p));
    return a;
}
__device__ __forceinline__ void cp16(uint32_t dst, const void* src) {
    asm volatile("cp.async.cg.shared.global [%0], [%1], 16;" :: "r"(dst), "l"(src) : "memory");
}
__device__ __forceinline__ void cp_commit() {
    asm volatile("cp.async.commit_group;" ::: "memory");
}
__device__ __forceinline__ void cp_wait0() {
    asm volatile("cp.async.wait_group 0;" ::: "memory");
}
__device__ __forceinline__ void cp_wait1() {
    asm volatile("cp.async.wait_group 1;" ::: "memory");
}
__device__ __forceinline__ void ldsm4(uint32_t* r, uint32_t addr) {
    asm volatile("ldmatrix.sync.aligned.m8n8.x4.shared.b16 {%0,%1,%2,%3}, [%4];"
                 : "=r"(r[0]), "=r"(r[1]), "=r"(r[2]), "=r"(r[3]) : "r"(addr));
}
__device__ __forceinline__ void mma16816(float* c, const uint32_t* a, const uint32_t* b) {
    asm volatile("mma.sync.aligned.m16n8k16.row.col.f32.f16.f16.f32 "
                 "{%0,%1,%2,%3}, {%4,%5,%6,%7}, {%8,%9}, {%0,%1,%2,%3};"
                 : "+f"(c[0]), "+f"(c[1]), "+f"(c[2]), "+f"(c[3])
                 : "r"(a[0]), "r"(a[1]), "r"(a[2]), "r"(a[3]), "r"(b[0]), "r"(b[1]));
}
__device__ __forceinline__ uint32_t sw128(uint32_t off) {
    return off ^ ((off >> 3) & 0x70);
}

// ---------------------------------------------------------------------------
// Helpers — sm_103a-only (feature-guarded; absent from compute_103 PTX)
// ---------------------------------------------------------------------------
#if defined(__CUDA_ARCH_FEAT_SM103_ALL)
__device__ __forceinline__ bool elect1() {
    uint32_t p;
    asm volatile("{ .reg .pred P; elect.sync _|P, 0xFFFFFFFF; selp.b32 %0, 1, 0, P; }" : "=r"(p));
    return p != 0;
}
__device__ __forceinline__ void mbar_init(uint32_t mbar, uint32_t cnt) {
    asm volatile("mbarrier.init.shared.b64 [%0], %1;" :: "r"(mbar), "r"(cnt) : "memory");
}
__device__ __forceinline__ void mbar_wait(uint32_t mbar, uint32_t parity) {
    asm volatile(
        "{\n\t.reg .pred P;\n\t"
        "LW_%=:\n\t"
        "mbarrier.try_wait.parity.acquire.cta.shared::cta.b64 P, [%0], %1, 0x989680;\n\t"
        "@P bra.uni LD_%=;\n\t"
        "bra.uni LW_%=;\n\t"
        "LD_%=:\n\t}"
        :: "r"(mbar), "r"(parity) : "memory");
}
__device__ __forceinline__ void tmem_alloc(uint32_t dst_smem, uint32_t ncols) {
    asm volatile("tcgen05.alloc.cta_group::1.sync.aligned.shared::cta.b32 [%0], %1;"
                 :: "r"(dst_smem), "r"(ncols) : "memory");
}
__device__ __forceinline__ void tmem_dealloc(uint32_t tmem, uint32_t ncols) {
    asm volatile("tcgen05.relinquish_alloc_permit.cta_group::1.sync.aligned;" ::: "memory");
    asm volatile("tcgen05.dealloc.cta_group::1.sync.aligned.b32 %0, %1;" :: "r"(tmem), "r"(ncols));
}
__device__ __forceinline__ void mma_f16_ss(uint32_t d, uint64_t ad, uint64_t bd,
                                           uint32_t idesc, uint32_t en) {
    asm volatile(
        "{\n\t.reg .pred p;\n\t"
        "setp.ne.u32 p, %4, 0;\n\t"
        "tcgen05.mma.cta_group::1.kind::f16 [%0], %1, %2, %3, {%5, %5, %5, %5}, p;\n\t}"
        :: "r"(d), "l"(ad), "l"(bd), "r"(idesc), "r"(en), "r"(0u) : "memory");
}
__device__ __forceinline__ void mma_commit(uint32_t mbar) {
    asm volatile("tcgen05.commit.cta_group::1.mbarrier::arrive::one.shared::cluster.b64 [%0];"
                 :: "r"(mbar) : "memory");
}
__device__ __forceinline__ void fence_async_shared() {
    asm volatile("fence.proxy.async.shared::cta;" ::: "memory");
}
__device__ __forceinline__ void tcgen05_fence_after() {
    asm volatile("tcgen05.fence::after_thread_sync;" ::: "memory");
}
__device__ __forceinline__ void tmem_wait_ld() {
    asm volatile("tcgen05.wait::ld.sync.aligned;" ::: "memory");
}
#define LDTM_X32(r, addr) \
    asm volatile( \
        "tcgen05.ld.sync.aligned.32x32b.x32.b32 " \
        "{%0, %1, %2, %3, %4, %5, %6, %7, " \
        " %8, %9, %10, %11, %12, %13, %14, %15, " \
        " %16, %17, %18, %19, %20, %21, %22, %23, " \
        " %24, %25, %26, %27, %28, %29, %30, %31}, [%32];" \
        : "=r"((r)[0]),  "=r"((r)[1]),  "=r"((r)[2]),  "=r"((r)[3]), \
          "=r"((r)[4]),  "=r"((r)[5]),  "=r"((r)[6]),  "=r"((r)[7]), \
          "=r"((r)[8]),  "=r"((r)[9]),  "=r"((r)[10]), "=r"((r)[11]), \
          "=r"((r)[12]), "=r"((r)[13]), "=r"((r)[14]), "=r"((r)[15]), \
          "=r"((r)[16]), "=r"((r)[17]), "=r"((r)[18]), "=r"((r)[19]), \
          "=r"((r)[20]), "=r"((r)[21]), "=r"((r)[22]), "=r"((r)[23]), \
          "=r"((r)[24]), "=r"((r)[25]), "=r"((r)[26]), "=r"((r)[27]), \
          "=r"((r)[28]), "=r"((r)[29]), "=r"((r)[30]), "=r"((r)[31]) \
        : "r"(addr))

static constexpr uint64_t DESC_BASE_SW128 =
    (2ULL << 61) | (1ULL << 46) | (64ULL << 32) | (1ULL << 16);
__device__ __forceinline__ uint64_t mkdesc(uint32_t base) {
    return DESC_BASE_SW128 | (uint64_t)((base >> 4) & 0x3FFF);
}
#endif  // __CUDA_ARCH_FEAT_SM103_ALL

// ---------------------------------------------------------------------------
// Split conversions: a = hi + lo in fp16
// ---------------------------------------------------------------------------
__global__ void convert_x_kernel(const float4* __restrict__ x)
{
    size_t i = (size_t)blockIdx.x * blockDim.x + threadIdx.x;
    float4 v = x[i];
    float f[4] = {v.x, v.y, v.z, v.w};
    union { __half h[4]; uint2 u; } p0, p1;
    #pragma unroll
    for (int k = 0; k < 4; k++) {
        __half a = __float2half_rn(f[k]);
        float  r = f[k] - __half2float(a);
        p0.h[k] = a;
        p1.h[k] = __float2half_rn(r);
    }
    ((uint2*)g_xs0)[i] = p0.u;
    ((uint2*)g_xs1)[i] = p1.u;
}

__global__ void convert_w_kernel(const float* __restrict__ W_gc, const float* __restrict__ W_d1,
                                 const float* __restrict__ b_gc, const float* __restrict__ b_d1)
{
    int i = blockIdx.x * blockDim.x + threadIdx.x;   // 524288
    int n = i >> 9, k = i & 511;
    float w = (n < HID) ? W_gc[k * HID + n] : W_d1[k * HID + (n - HID)];
    w *= 1024.0f;            // exact pow2 scale; keeps lo-split out of fp16 subnormals
    __half a = __float2half_rn(w);
    float  r = w - __half2float(a);
    g_ws0[(size_t)n * K_DIM + k] = a;
    g_ws1[(size_t)n * K_DIM + k] = __float2half_rn(r);
    if (i < N_CAT) g_bias[i] = (i < HID) ? b_gc[i] : b_d1[i - HID];
}

// ---------------------------------------------------------------------------
// GEMM: g_pre = ((x0+x1) @ (w0+w1)^T) * 2^-10 + bias  (3 split-products)
// CTA tile 128x256. tcgen05 double-buffered on sm_103a; HMMA on compute_103.
// ---------------------------------------------------------------------------
#define GM 128
#define GN 256
#define STAGE_BYTES 98304                 /* A0 16K | A1 16K | B0 32K | B1 32K */
#define GEMM_SMEM  (1024 + 2 * STAGE_BYTES)

__global__ void __launch_bounds__(256, 1) gemm_kernel()
{
    extern __shared__ char smem[];
    const int tid  = threadIdx.x;
    const int lane = tid & 31;
    const int wid  = tid >> 5;
    const size_t m0 = (size_t)blockIdx.y * GM;
    const int    n0 = blockIdx.x * GN;

#if defined(__CUDA_ARCH_FEAT_SM103_ALL)
    // ======================= tcgen05 path (sm_103a) =======================
    __shared__ __align__(16) uint32_t s_ctrl[4];     // [0]=tmem ptr; [2..3]=mbarrier
    char* tp = (char*)(((uintptr_t)smem + 1023) & ~(uintptr_t)1023);
    const uint32_t SAu  = smem_u32(tp);
    const uint32_t ctrl = smem_u32(&s_ctrl[0]);
    const uint32_t mbar = smem_u32(&s_ctrl[2]);

    if (wid == 0) tmem_alloc(ctrl, 256);
    if (tid == 0) mbar_init(mbar, 1);
    __syncthreads();
    uint32_t tmem;
    asm volatile("ld.shared.b32 %0, [%1];" : "=r"(tmem) : "r"(ctrl));

    const uint32_t IDESC = (1u << 4) | ((GN / 8) << 17) | ((GM / 16) << 24);

    auto load_stage = [&](int c, int s) {
        char* base = tp + s * STAGE_BYTES;
        #pragma unroll
        for (int i = 0; i < 8; i++) {                // A: 2048 x 16B
            int u = tid + 256 * i;
            int p = u >> 10, r = u & 1023, row = r >> 3, j = r & 7;
            const __half* sa = (p ? g_xs1 : g_xs0) + (m0 + row) * K_DIM + c * 64 + j * 8;
            cp16(smem_u32(base + p * 16384 + sw128(row * 128 + j * 16)), sa);
        }
        #pragma unroll
        for (int i = 0; i < 16; i++) {               // B: 4096 x 16B
            int u = tid + 256 * i;
            int p = u >> 11, r = u & 2047, row = r >> 3, j = r & 7;
            const __half* sbp = (p ? g_ws1 : g_ws0) + (size_t)(n0 + row) * K_DIM + c * 64 + j * 8;
            cp16(smem_u32(base + 32768 + p * 32768 + sw128(row * 128 + j * 16)), sbp);
        }
        cp_commit();
    };

    load_stage(0, 0);
    load_stage(1, 1);

    #pragma unroll 1
    for (int c = 0; c < K_DIM / 64; c++) {           // 8 chunks of K=64
        if (c < 7) cp_wait1(); else cp_wait0();      // chunk c's loads complete
        fence_async_shared();
        __syncthreads();

        if (wid == 0 && elect1()) {
            uint32_t sb = SAu + (c & 1) * STAGE_BYTES;
            uint64_t dA0 = mkdesc(sb),         dA1 = mkdesc(sb + 16384);
            uint64_t dB0 = mkdesc(sb + 32768), dB1 = mkdesc(sb + 65536);
            #pragma unroll
            for (int ks = 0; ks < 4; ks++) {
                uint32_t en = (c == 0 && ks == 0) ? 0u : 1u;
                mma_f16_ss(tmem, dA0 + 2 * ks, dB0 + 2 * ks, IDESC, en);
                mma_f16_ss(tmem, dA0 + 2 * ks, dB1 + 2 * ks, IDESC, 1u);
                mma_f16_ss(tmem, dA1 + 2 * ks, dB0 + 2 * ks, IDESC, 1u);
            }
            mma_commit(mbar);
        }
        mbar_wait(mbar, c & 1);                      // chunk c MMAs done -> stage reusable
        if (c + 2 < K_DIM / 64)
            load_stage(c + 2, c & 1);                // overlaps chunk c+1's MMAs
    }
    tcgen05_fence_after();

    // epilogue: warp w -> rows 32*(w&3), cols 128*(w>>2)..+127
    {
        size_t row = m0 + (wid & 3) * 32 + lane;
        int colb = (wid >> 2) * 128;
        float* cp = g_pre + row * N_CAT + n0 + colb;
        const float sc = 1.0f / 1024.0f;
        #pragma unroll
        for (int cb = 0; cb < 4; cb++) {
            uint32_t r[32];
            LDTM_X32(r, tmem + colb + cb * 32);
            tmem_wait_ld();
            #pragma unroll
            for (int j = 0; j < 32; j += 4) {
                float4 v;
                v.x = __uint_as_float(r[j + 0]) * sc + g_bias[n0 + colb + cb * 32 + j + 0];
                v.y = __uint_as_float(r[j + 1]) * sc + g_bias[n0 + colb + cb * 32 + j + 1];
                v.z = __uint_as_float(r[j + 2]) * sc + g_bias[n0 + colb + cb * 32 + j + 2];
                v.w = __uint_as_float(r[j + 3]) * sc + g_bias[n0 + colb + cb * 32 + j + 3];
                *(float4*)(cp + cb * 32 + j) = v;
            }
        }
    }
    __syncthreads();
    if (wid == 0) tmem_dealloc(tmem, 256);

#else
    // ========= HMMA fallback (compute_103): two 128-wide halves ==========
    const uint32_t sb = smem_u32(smem);
    const int wm = (wid >> 2) * 64;
    const int wn = (wid & 3) * 32;
    #define ROWB 80
    #define SPL_BYTES (128 * ROWB)
    #define HSTAGE (4 * SPL_BYTES)

    #pragma unroll 1
    for (int nh = 0; nh < 2; nh++) {
        const int n0h = n0 + 128 * nh;

        float c[4][4][4];
        #pragma unroll
        for (int i = 0; i < 4; i++)
            #pragma unroll
            for (int j = 0; j < 4; j++)
                #pragma unroll
                for (int k = 0; k < 4; k++) c[i][j][k] = 0.f;

        auto load_stage = [&](int cc, int st) {
            uint32_t base = sb + st * HSTAGE;
            #pragma unroll
            for (int i = 0; i < 4; i++) {
                int u = tid + 256 * i;
                int p = u >> 9, r = (u >> 2) & 127, j = u & 3;
                const __half* src = (p ? g_xs1 : g_xs0) + (m0 + r) * K_DIM + cc * 32 + j * 8;
                cp16(base + p * SPL_BYTES + r * ROWB + j * 16, src);
            }
            #pragma unroll
            for (int i = 0; i < 4; i++) {
                int u = tid + 256 * i;
                int p = u >> 9, r = (u >> 2) & 127, j = u & 3;
                const __half* src = (p ? g_ws1 : g_ws0) + (size_t)(n0h + r) * K_DIM + cc * 32 + j * 8;
                cp16(base + 2 * SPL_BYTES + p * SPL_BYTES + r * ROWB + j * 16, src);
            }
            cp_commit();
        };

        auto compute_stage = [&](int st) {
            uint32_t Ab = sb + st * HSTAGE;
            uint32_t Bb = Ab + 2 * SPL_BYTES;
            #pragma unroll
            for (int kk = 0; kk < 2; kk++) {
                uint32_t a[2][4][4];
                uint32_t b[2][4][2];
                #pragma unroll
                for (int p = 0; p < 2; p++)
                    #pragma unroll
                    for (int mi = 0; mi < 4; mi++) {
                        uint32_t addr = Ab + p * SPL_BYTES
                                      + (wm + 16 * mi + (lane & 15)) * ROWB
                                      + kk * 32 + (lane >> 4) * 16;
                        ldsm4(a[p][mi], addr);
                    }
                #pragma unroll
                for (int p = 0; p < 2; p++)
                    #pragma unroll
                    for (int jj = 0; jj < 2; jj++) {
                        uint32_t nr = wn + 16 * jj + ((lane >> 4) & 1) * 8 + (lane & 7);
                        uint32_t addr = Bb + p * SPL_BYTES + nr * ROWB
                                      + kk * 32 + ((lane >> 3) & 1) * 16;
                        uint32_t r4[4];
                        ldsm4(r4, addr);
                        b[p][2 * jj][0]     = r4[0]; b[p][2 * jj][1]     = r4[1];
                        b[p][2 * jj + 1][0] = r4[2]; b[p][2 * jj + 1][1] = r4[3];
                    }
                #pragma unroll
                for (int mi = 0; mi < 4; mi++)
                    #pragma unroll
                    for (int nj = 0; nj < 4; nj++) {
                        mma16816(c[mi][nj], a[0][mi], b[0][nj]);
                        mma16816(c[mi][nj], a[0][mi], b[1][nj]);
                        mma16816(c[mi][nj], a[1][mi], b[0][nj]);
                    }
            }
        };

        load_stage(0, 0);
        #pragma unroll 1
        for (int cc = 0; cc < K_DIM / 32; cc++) {
            cp_wait0();
            __syncthreads();
            if (cc + 1 < K_DIM / 32) load_stage(cc + 1, (cc + 1) & 1);
            compute_stage(cc & 1);
        }
        __syncthreads();

        const float sc = 1.0f / 1024.0f;
        const int g = lane >> 2, t4 = lane & 3;
        #pragma unroll
        for (int mi = 0; mi < 4; mi++) {
            #pragma unroll
            for (int nj = 0; nj < 4; nj++) {
                int col = n0h + wn + 8 * nj + t4 * 2;
                float b0 = g_bias[col], b1 = g_bias[col + 1];
                size_t row = m0 + wm + 16 * mi + g;
                float2 v0 = {c[mi][nj][0] * sc + b0, c[mi][nj][1] * sc + b1};
                *(float2*)(g_pre + row * N_CAT + col) = v0;
                float2 v1 = {c[mi][nj][2] * sc + b0, c[mi][nj][3] * sc + b1};
                *(float2*)(g_pre + (row + 8) * N_CAT + col) = v1;
            }
        }
    }
    #undef ROWB
    #undef SPL_BYTES
    #undef HSTAGE
#endif
}

// ---------------------------------------------------------------------------
// Recurrence: neuron j = 4*tid + q; float4 gathers; g_pre prefetched one
// timestep ahead to hide DRAM latency.
// ---------------------------------------------------------------------------
__global__ void __launch_bounds__(128) recur_kernel(
    const float* __restrict__ W_pc, const float* __restrict__ b_pc,
    const float* __restrict__ W_d1, const float* __restrict__ W_d2,
    const float* __restrict__ b_d2, float* __restrict__ out)
{
    const int b    = blockIdx.x;
    const int tid  = threadIdx.x;
    const int lane = tid & 31;
    const int w    = tid >> 5;

    __shared__ unsigned gcmask[16];
    __shared__ unsigned pcmask[16];
    __shared__ float    sred[OUT_N * 4];

    float m1[4] = {0.f, 0.f, 0.f, 0.f};
    float m2[4] = {0.f, 0.f, 0.f, 0.f};
    float m3[4] = {0.f, 0.f, 0.f, 0.f};
    float oacc[OUT_N] = {0.f, 0.f, 0.f, 0.f, 0.f, 0.f, 0.f};

    float4 bpc4 = ((const float4*)b_pc)[tid];
    float bpc[4] = {bpc4.x, bpc4.y, bpc4.z, bpc4.w};

    const float* pre0 = g_pre + (size_t)b * N_CAT;
    float4 p4  = ((const float4*)pre0)[tid];
    float4 p4b = ((const float4*)(pre0 + HID))[tid];

    for (int t = 0; t < T_STEPS; t++) {
        // prefetch next step's pre-activations (issued now, consumed next iter)
        float4 n4 = p4, n4b = p4b;
        if (t + 1 < T_STEPS) {
            const float* pn = g_pre + ((size_t)(t + 1) * B_ROWS + b) * N_CAT;
            n4  = ((const float4*)pn)[tid];
            n4b = ((const float4*)(pn + HID))[tid];
        }

        // ---- LIF1 ----
        float pr[4] = {p4.x, p4.y, p4.z, p4.w};
        #pragma unroll
        for (int q = 0; q < 4; q++) {
            float v = 0.5f * (m1[q] + pr[q]);
            bool  s = v > 1.0f;
            m1[q]   = s ? 0.f : v;
            unsigned bal = __ballot_sync(0xffffffffu, s);
            if (lane == 0) gcmask[4 * q + w] = bal;
        }
        __syncthreads();

        // ---- pc_pre = gc @ W_pc + b_pc (sparse float4 row gather) ----
        float a2[4] = {bpc[0], bpc[1], bpc[2], bpc[3]};
        #pragma unroll 1
        for (int mw = 0; mw < 16; mw++) {
            unsigned mm = gcmask[mw];
            int q = mw >> 2, wb = (mw & 3) << 7;
            while (mm) {
                int l = __ffs(mm) - 1;
                mm &= mm - 1;
                int row = wb + 4 * l + q;
                float4 wv = ((const float4*)(W_pc + (size_t)row * HID))[tid];
                a2[0] += wv.x; a2[1] += wv.y; a2[2] += wv.z; a2[3] += wv.w;
            }
        }

        // ---- LIF2 ----
        #pragma unroll
        for (int q = 0; q < 4; q++) {
            float v = 0.5f * (m2[q] + a2[q]);
            bool  s = v > 1.0f;
            m2[q]   = s ? 0.f : v;
            unsigned bal = __ballot_sync(0xffffffffu, s);
            if (lane == 0) pcmask[4 * q + w] = bal;
        }
        __syncthreads();

        // ---- d1_pre = precomputed x-part + pc @ W_d1_bottom ----
        float a3[4] = {p4b.x, p4b.y, p4b.z, p4b.w};
        #pragma unroll 1
        for (int mw = 0; mw < 16; mw++) {
            unsigned mm = pcmask[mw];
            int q = mw >> 2, wb = (mw & 3) << 7;
            while (mm) {
                int l = __ffs(mm) - 1;
                mm &= mm - 1;
                int row = HID + wb + 4 * l + q;
                float4 wv = ((const float4*)(W_d1 + (size_t)row * HID))[tid];
                a3[0] += wv.x; a3[1] += wv.y; a3[2] += wv.z; a3[3] += wv.w;
            }
        }

        // ---- LIF3 -> readout ----
        #pragma unroll
        for (int q = 0; q < 4; q++) {
            float v = 0.5f * (m3[q] + a3[q]);
            bool  s = v > 1.0f;
            m3[q]   = s ? 0.f : v;
            if (s) {
                const float* wr = W_d2 + (size_t)(4 * tid + q) * OUT_N;
                #pragma unroll
                for (int o = 0; o < OUT_N; o++) oacc[o] += wr[o];
            }
        }
        __syncthreads();

        p4 = n4; p4b = n4b;
    }

    #pragma unroll
    for (int o = 0; o < OUT_N; o++) {
        float v = oacc[o];
        #pragma unroll
        for (int off = 16; off; off >>= 1) v += __shfl_down_sync(0xffffffffu, v, off);
        if (lane == 0) sred[o * 4 + w] = v;
    }
    __syncthreads();
    if (tid < OUT_N) {
        float s = sred[tid * 4] + sred[tid * 4 + 1] + sred[tid * 4 + 2] + sred[tid * 4 + 3];
        out[(size_t)b * OUT_N + tid] = s * (1.0f / (float)T_STEPS) + b_d2[tid];
    }
}

// ---------------------------------------------------------------------------
extern "C" void kernel_launch(void* const* d_in, const int* in_sizes, int n_in,
                              void* d_out, int out_size)
{
    const float* x    = (const float*)d_in[0];
    const float* W_gc = (const float*)d_in[1];
    const float* b_gc = (const float*)d_in[2];
    const float* W_pc = (const float*)d_in[3];
    const float* b_pc = (const float*)d_in[4];
    const float* W_d1 = (const float*)d_in[5];
    const float* b_d1 = (const float*)d_in[6];
    const float* W_d2 = (const float*)d_in[7];
    const float* b_d2 = (const float*)d_in[8];
    float* out = (float*)d_out;
    (void)in_sizes; (void)n_in; (void)out_size;

    cudaFuncSetAttribute(gemm_kernel, cudaFuncAttributeMaxDynamicSharedMemorySize, GEMM_SMEM);

    convert_x_kernel<<<((size_t)M_TOT * K_DIM / 4) / 256, 256>>>((const float4*)x);
    convert_w_kernel<<<(N_CAT * K_DIM) / 256, 256>>>(W_gc, W_d1, b_gc, b_d1);

    dim3 grid(N_CAT / GN, M_TOT / GM);   // (4, 2048); x fastest -> A tiles reuse L2
    gemm_kernel<<<grid, 256, GEMM_SMEM>>>();

    recur_kernel<<<B_ROWS, 128>>>(W_pc, b_pc, W_d1, W_d2, b_d2, out);
}

// round 6
// speedup vs baseline: 4.7431x; 1.4115x over previous
#include <cuda_runtime.h>
#include <cuda_fp16.h>
#include <cstdint>
#include <cstddef>

#define T_STEPS 16
#define B_ROWS  16384
#define HID     512
#define OUT_N   7
#define M_TOT   (T_STEPS * B_ROWS)   /* 262144 */
#define N_CAT   1024
#define K_DIM   512

// ---------------------------------------------------------------------------
// Static device scratch (no runtime allocation)
// ---------------------------------------------------------------------------
__device__ float  g_pre[(size_t)M_TOT * N_CAT];     // [T*B, 1024] pre-activations
__device__ __half g_xs0[(size_t)M_TOT * K_DIM];     // x hi split
__device__ __half g_xs1[(size_t)M_TOT * K_DIM];     // x lo split
__device__ __half g_ws0[(size_t)N_CAT * K_DIM];     // (1024*W)^T hi split, [N,K]
__device__ __half g_ws1[(size_t)N_CAT * K_DIM];     // (1024*W)^T lo split
__device__ float  g_bias[N_CAT];

// ---------------------------------------------------------------------------
// Helpers — baseline PTX (sm_80+, valid in every compilation pass)
// ---------------------------------------------------------------------------
__device__ __forceinline__ uint32_t smem_u32(const void* p) {
    uint32_t a;
    asm("{ .reg .u64 t; cvta.to.shared.u64 t, %1; cvt.u32.u64 %0, t; }" : "=r"(a) : "l"(p));
    return a;
}
__device__ __forceinline__ void cp16(uint32_t dst, const void* src) {
    asm volatile("cp.async.cg.shared.global [%0], [%1], 16;" :: "r"(dst), "l"(src) : "memory");
}
__device__ __forceinline__ void cp_commit() {
    asm volatile("cp.async.commit_group;" ::: "memory");
}
__device__ __forceinline__ void cp_wait0() {
    asm volatile("cp.async.wait_group 0;" ::: "memory");
}
__device__ __forceinline__ void cp_wait1() {
    asm volatile("cp.async.wait_group 1;" ::: "memory");
}
__device__ __forceinline__ void ldsm4(uint32_t* r, uint32_t addr) {
    asm volatile("ldmatrix.sync.aligned.m8n8.x4.shared.b16 {%0,%1,%2,%3}, [%4];"
                 : "=r"(r[0]), "=r"(r[1]), "=r"(r[2]), "=r"(r[3]) : "r"(addr));
}
__device__ __forceinline__ void mma16816(float* c, const uint32_t* a, const uint32_t* b) {
    asm volatile("mma.sync.aligned.m16n8k16.row.col.f32.f16.f16.f32 "
                 "{%0,%1,%2,%3}, {%4,%5,%6,%7}, {%8,%9}, {%0,%1,%2,%3};"
                 : "+f"(c[0]), "+f"(c[1]), "+f"(c[2]), "+f"(c[3])
                 : "r"(a[0]), "r"(a[1]), "r"(a[2]), "r"(a[3]), "r"(b[0]), "r"(b[1]));
}
__device__ __forceinline__ uint32_t sw64(uint32_t off) {
    return off ^ ((off >> 3) & 0x30);
}

// ---------------------------------------------------------------------------
// Helpers — sm_103a-only (feature-guarded; absent from compute_103 PTX)
// ---------------------------------------------------------------------------
#if defined(__CUDA_ARCH_FEAT_SM103_ALL)
__device__ __forceinline__ bool elect1() {
    uint32_t p;
    asm volatile("{ .reg .pred P; elect.sync _|P, 0xFFFFFFFF; selp.b32 %0, 1, 0, P; }" : "=r"(p));
    return p != 0;
}
__device__ __forceinline__ void mbar_init(uint32_t mbar, uint32_t cnt) {
    asm volatile("mbarrier.init.shared.b64 [%0], %1;" :: "r"(mbar), "r"(cnt) : "memory");
}
__device__ __forceinline__ void mbar_wait(uint32_t mbar, uint32_t parity) {
    asm volatile(
        "{\n\t.reg .pred P;\n\t"
        "LW_%=:\n\t"
        "mbarrier.try_wait.parity.acquire.cta.shared::cta.b64 P, [%0], %1, 0x989680;\n\t"
        "@P bra.uni LD_%=;\n\t"
        "bra.uni LW_%=;\n\t"
        "LD_%=:\n\t}"
        :: "r"(mbar), "r"(parity) : "memory");
}
__device__ __forceinline__ void tmem_alloc(uint32_t dst_smem, uint32_t ncols) {
    asm volatile("tcgen05.alloc.cta_group::1.sync.aligned.shared::cta.b32 [%0], %1;"
                 :: "r"(dst_smem), "r"(ncols) : "memory");
}
__device__ __forceinline__ void tmem_dealloc(uint32_t tmem, uint32_t ncols) {
    asm volatile("tcgen05.relinquish_alloc_permit.cta_group::1.sync.aligned;" ::: "memory");
    asm volatile("tcgen05.dealloc.cta_group::1.sync.aligned.b32 %0, %1;" :: "r"(tmem), "r"(ncols));
}
__device__ __forceinline__ void mma_f16_ss(uint32_t d, uint64_t ad, uint64_t bd,
                                           uint32_t idesc, uint32_t en) {
    asm volatile(
        "{\n\t.reg .pred p;\n\t"
        "setp.ne.u32 p, %4, 0;\n\t"
        "tcgen05.mma.cta_group::1.kind::f16 [%0], %1, %2, %3, {%5, %5, %5, %5}, p;\n\t}"
        :: "r"(d), "l"(ad), "l"(bd), "r"(idesc), "r"(en), "r"(0u) : "memory");
}
__device__ __forceinline__ void mma_commit(uint32_t mbar) {
    asm volatile("tcgen05.commit.cta_group::1.mbarrier::arrive::one.shared::cluster.b64 [%0];"
                 :: "r"(mbar) : "memory");
}
__device__ __forceinline__ void fence_async_shared() {
    asm volatile("fence.proxy.async.shared::cta;" ::: "memory");
}
__device__ __forceinline__ void tcgen05_fence_after() {
    asm volatile("tcgen05.fence::after_thread_sync;" ::: "memory");
}
__device__ __forceinline__ void tmem_wait_ld() {
    asm volatile("tcgen05.wait::ld.sync.aligned;" ::: "memory");
}
#define LDTM_X32(r, addr) \
    asm volatile( \
        "tcgen05.ld.sync.aligned.32x32b.x32.b32 " \
        "{%0, %1, %2, %3, %4, %5, %6, %7, " \
        " %8, %9, %10, %11, %12, %13, %14, %15, " \
        " %16, %17, %18, %19, %20, %21, %22, %23, " \
        " %24, %25, %26, %27, %28, %29, %30, %31}, [%32];" \
        : "=r"((r)[0]),  "=r"((r)[1]),  "=r"((r)[2]),  "=r"((r)[3]), \
          "=r"((r)[4]),  "=r"((r)[5]),  "=r"((r)[6]),  "=r"((r)[7]), \
          "=r"((r)[8]),  "=r"((r)[9]),  "=r"((r)[10]), "=r"((r)[11]), \
          "=r"((r)[12]), "=r"((r)[13]), "=r"((r)[14]), "=r"((r)[15]), \
          "=r"((r)[16]), "=r"((r)[17]), "=r"((r)[18]), "=r"((r)[19]), \
          "=r"((r)[20]), "=r"((r)[21]), "=r"((r)[22]), "=r"((r)[23]), \
          "=r"((r)[24]), "=r"((r)[25]), "=r"((r)[26]), "=r"((r)[27]), \
          "=r"((r)[28]), "=r"((r)[29]), "=r"((r)[30]), "=r"((r)[31]) \
        : "r"(addr))

// SW64 K-major descriptor: layout=4, version=1 (Blackwell), SBO=32 (512B = 8 rows
// x 64B), LBO=1 (16B inner stride).
static constexpr uint64_t DESC_BASE_SW64 =
    (4ULL << 61) | (1ULL << 46) | (32ULL << 32) | (1ULL << 16);
__device__ __forceinline__ uint64_t mkdesc64(uint32_t base) {
    return DESC_BASE_SW64 | (uint64_t)((base >> 4) & 0x3FFF);
}
#endif  // __CUDA_ARCH_FEAT_SM103_ALL

// ---------------------------------------------------------------------------
// Split conversions: a = hi + lo in fp16
// ---------------------------------------------------------------------------
__global__ void convert_x_kernel(const float4* __restrict__ x)
{
    size_t i = (size_t)blockIdx.x * blockDim.x + threadIdx.x;
    float4 v = x[i];
    float f[4] = {v.x, v.y, v.z, v.w};
    union { __half h[4]; uint2 u; } p0, p1;
    #pragma unroll
    for (int k = 0; k < 4; k++) {
        __half a = __float2half_rn(f[k]);
        float  r = f[k] - __half2float(a);
        p0.h[k] = a;
        p1.h[k] = __float2half_rn(r);
    }
    ((uint2*)g_xs0)[i] = p0.u;
    ((uint2*)g_xs1)[i] = p1.u;
}

__global__ void convert_w_kernel(const float* __restrict__ W_gc, const float* __restrict__ W_d1,
                                 const float* __restrict__ b_gc, const float* __restrict__ b_d1)
{
    int i = blockIdx.x * blockDim.x + threadIdx.x;   // 524288
    int n = i >> 9, k = i & 511;
    float w = (n < HID) ? W_gc[k * HID + n] : W_d1[k * HID + (n - HID)];
    w *= 1024.0f;            // exact pow2 scale; keeps lo-split out of fp16 subnormals
    __half a = __float2half_rn(w);
    float  r = w - __half2float(a);
    g_ws0[(size_t)n * K_DIM + k] = a;
    g_ws1[(size_t)n * K_DIM + k] = __float2half_rn(r);
    if (i < N_CAT) g_bias[i] = (i < HID) ? b_gc[i] : b_d1[i - HID];
}

// ---------------------------------------------------------------------------
// GEMM: g_pre = ((x0+x1) @ (w0+w1)^T) * 2^-10 + bias  (3 split-products)
// CTA tile 256x256 (two 128x256 TMEM accumulators). KC=32, SW64, 3-stage
// cp.async ring with per-stage mbarriers. HMMA fallback on compute_103.
// ---------------------------------------------------------------------------
#define GM 256
#define GN 256
#define KC 32
#define NCHUNK (K_DIM / KC)               /* 16 */
#define STAGE_BYTES 65536                 /* A: 2x16K | B: 2x16K */
#define GEMM_SMEM (1024 + 3 * STAGE_BYTES)

__global__ void __launch_bounds__(256, 1) gemm_kernel()
{
    extern __shared__ char smem[];
    const int tid  = threadIdx.x;
    const int lane = tid & 31;
    const int wid  = tid >> 5;
    const size_t m0 = (size_t)blockIdx.y * GM;
    const int    n0 = blockIdx.x * GN;

#if defined(__CUDA_ARCH_FEAT_SM103_ALL)
    // ======================= tcgen05 path (sm_103a) =======================
    __shared__ __align__(16) uint32_t s_ctrl[8];  // [0]=tmem ptr; [2..7]=3 mbarriers
    char* tp = (char*)(((uintptr_t)smem + 1023) & ~(uintptr_t)1023);
    const uint32_t SAu   = smem_u32(tp);
    const uint32_t ctrl  = smem_u32(&s_ctrl[0]);
    const uint32_t mbar0 = smem_u32(&s_ctrl[2]);   // mbar[s] = mbar0 + 8*s

    if (wid == 0) tmem_alloc(ctrl, 512);
    if (tid == 0) {
        mbar_init(mbar0, 1);
        mbar_init(mbar0 + 8, 1);
        mbar_init(mbar0 + 16, 1);
    }
    __syncthreads();
    uint32_t tmem;
    asm volatile("ld.shared.b32 %0, [%1];" : "=r"(tmem) : "r"(ctrl));

    const uint32_t IDESC = (1u << 4) | ((GN / 8) << 17) | (8u << 24);   // M=128,N=256,f16

    auto load_stage = [&](int c, int s) {
        char* base = tp + s * STAGE_BYTES;
        #pragma unroll
        for (int i = 0; i < 8; i++) {                // A: 2048 x 16B (2 splits x 256r x 64B)
            int u = tid + 256 * i;
            int p = u >> 10, rem = u & 1023, row = rem >> 2, j = rem & 3;
            const __half* sa = (p ? g_xs1 : g_xs0) + (m0 + row) * K_DIM + c * KC + j * 8;
            cp16(smem_u32(base + p * 16384 + sw64(row * 64 + j * 16)), sa);
        }
        #pragma unroll
        for (int i = 0; i < 8; i++) {                // B: 2048 x 16B
            int u = tid + 256 * i;
            int p = u >> 10, rem = u & 1023, row = rem >> 2, j = rem & 3;
            const __half* sbp = (p ? g_ws1 : g_ws0) + (size_t)(n0 + row) * K_DIM + c * KC + j * 8;
            cp16(smem_u32(base + 32768 + p * 16384 + sw64(row * 64 + j * 16)), sbp);
        }
        cp_commit();
    };

    load_stage(0, 0);
    load_stage(1, 1);

    #pragma unroll 1
    for (int c = 0; c < NCHUNK; c++) {
        if (c < NCHUNK - 2) cp_wait1(); else cp_wait0();   // chunk c's loads done
        fence_async_shared();
        __syncthreads();

        if (wid == 0 && elect1()) {
            uint32_t sb = SAu + (c % 3) * STAGE_BYTES;
            #pragma unroll
            for (int ks = 0; ks < 2; ks++) {
                #pragma unroll
                for (int h = 0; h < 2; h++) {
                    uint64_t dA0 = mkdesc64(sb + h * 8192) + 2 * ks;
                    uint64_t dA1 = mkdesc64(sb + 16384 + h * 8192) + 2 * ks;
                    uint64_t dB0 = mkdesc64(sb + 32768) + 2 * ks;
                    uint64_t dB1 = mkdesc64(sb + 49152) + 2 * ks;
                    uint32_t d   = tmem + 256 * h;
                    uint32_t en  = (c == 0 && ks == 0) ? 0u : 1u;
                    mma_f16_ss(d, dA0, dB0, IDESC, en);
                    mma_f16_ss(d, dA0, dB1, IDESC, 1u);
                    mma_f16_ss(d, dA1, dB0, IDESC, 1u);
                }
            }
            mma_commit(mbar0 + 8 * (c % 3));
        }

        if (c + 2 < NCHUNK) {
            if (c >= 1) {
                // stage (c+2)%3 was used by chunk c-1; wait its MMAs
                int s = (c + 2) % 3;
                mbar_wait(mbar0 + 8 * s, ((c - 1) / 3) & 1);
            }
            load_stage(c + 2, (c + 2) % 3);
        }
    }
    // all MMAs done (last chunk = NCHUNK-1, stage (NCHUNK-1)%3, use (NCHUNK-1)/3)
    mbar_wait(mbar0 + 8 * ((NCHUNK - 1) % 3), ((NCHUNK - 1) / 3) & 1);
    tcgen05_fence_after();

    // epilogue: warp w -> half h=w>>2 (rows m0+128h+32*(w&3)), cols 0..255
    {
        int h = wid >> 2, sub = wid & 3;
        size_t row = m0 + h * 128 + sub * 32 + lane;
        float* cp = g_pre + row * N_CAT + n0;
        const float sc = 1.0f / 1024.0f;
        #pragma unroll
        for (int cb = 0; cb < 8; cb++) {
            uint32_t r[32];
            LDTM_X32(r, tmem + h * 256 + cb * 32);
            tmem_wait_ld();
            #pragma unroll
            for (int j = 0; j < 32; j += 4) {
                float4 v;
                v.x = __uint_as_float(r[j + 0]) * sc + g_bias[n0 + cb * 32 + j + 0];
                v.y = __uint_as_float(r[j + 1]) * sc + g_bias[n0 + cb * 32 + j + 1];
                v.z = __uint_as_float(r[j + 2]) * sc + g_bias[n0 + cb * 32 + j + 2];
                v.w = __uint_as_float(r[j + 3]) * sc + g_bias[n0 + cb * 32 + j + 3];
                *(float4*)(cp + cb * 32 + j) = v;
            }
        }
    }
    __syncthreads();
    if (wid == 0) tmem_dealloc(tmem, 512);

#else
    // ========= HMMA fallback (compute_103): four 128x128 sub-tiles =========
    const uint32_t sb = smem_u32(smem);
    const int wm = (wid >> 2) * 64;
    const int wn = (wid & 3) * 32;
    #define ROWB 80
    #define SPL_BYTES (128 * ROWB)
    #define HSTAGE (4 * SPL_BYTES)

    #pragma unroll 1
    for (int mh = 0; mh < 2; mh++) {
        const size_t m0h = m0 + 128 * mh;
        #pragma unroll 1
        for (int nh = 0; nh < 2; nh++) {
            const int n0h = n0 + 128 * nh;

            float c[4][4][4];
            #pragma unroll
            for (int i = 0; i < 4; i++)
                #pragma unroll
                for (int j = 0; j < 4; j++)
                    #pragma unroll
                    for (int k = 0; k < 4; k++) c[i][j][k] = 0.f;

            auto load_stage = [&](int cc, int st) {
                uint32_t base = sb + st * HSTAGE;
                #pragma unroll
                for (int i = 0; i < 4; i++) {
                    int u = tid + 256 * i;
                    int p = u >> 9, r = (u >> 2) & 127, j = u & 3;
                    const __half* src = (p ? g_xs1 : g_xs0) + (m0h + r) * K_DIM + cc * 32 + j * 8;
                    cp16(base + p * SPL_BYTES + r * ROWB + j * 16, src);
                }
                #pragma unroll
                for (int i = 0; i < 4; i++) {
                    int u = tid + 256 * i;
                    int p = u >> 9, r = (u >> 2) & 127, j = u & 3;
                    const __half* src = (p ? g_ws1 : g_ws0) + (size_t)(n0h + r) * K_DIM + cc * 32 + j * 8;
                    cp16(base + 2 * SPL_BYTES + p * SPL_BYTES + r * ROWB + j * 16, src);
                }
                cp_commit();
            };

            auto compute_stage = [&](int st) {
                uint32_t Ab = sb + st * HSTAGE;
                uint32_t Bb = Ab + 2 * SPL_BYTES;
                #pragma unroll
                for (int kk = 0; kk < 2; kk++) {
                    uint32_t a[2][4][4];
                    uint32_t b[2][4][2];
                    #pragma unroll
                    for (int p = 0; p < 2; p++)
                        #pragma unroll
                        for (int mi = 0; mi < 4; mi++) {
                            uint32_t addr = Ab + p * SPL_BYTES
                                          + (wm + 16 * mi + (lane & 15)) * ROWB
                                          + kk * 32 + (lane >> 4) * 16;
                            ldsm4(a[p][mi], addr);
                        }
                    #pragma unroll
                    for (int p = 0; p < 2; p++)
                        #pragma unroll
                        for (int jj = 0; jj < 2; jj++) {
                            uint32_t nr = wn + 16 * jj + ((lane >> 4) & 1) * 8 + (lane & 7);
                            uint32_t addr = Bb + p * SPL_BYTES + nr * ROWB
                                          + kk * 32 + ((lane >> 3) & 1) * 16;
                            uint32_t r4[4];
                            ldsm4(r4, addr);
                            b[p][2 * jj][0]     = r4[0]; b[p][2 * jj][1]     = r4[1];
                            b[p][2 * jj + 1][0] = r4[2]; b[p][2 * jj + 1][1] = r4[3];
                        }
                    #pragma unroll
                    for (int mi = 0; mi < 4; mi++)
                        #pragma unroll
                        for (int nj = 0; nj < 4; nj++) {
                            mma16816(c[mi][nj], a[0][mi], b[0][nj]);
                            mma16816(c[mi][nj], a[0][mi], b[1][nj]);
                            mma16816(c[mi][nj], a[1][mi], b[0][nj]);
                        }
                }
            };

            load_stage(0, 0);
            #pragma unroll 1
            for (int cc = 0; cc < K_DIM / 32; cc++) {
                cp_wait0();
                __syncthreads();
                if (cc + 1 < K_DIM / 32) load_stage(cc + 1, (cc + 1) & 1);
                compute_stage(cc & 1);
            }
            __syncthreads();

            const float sc = 1.0f / 1024.0f;
            const int g = lane >> 2, t4 = lane & 3;
            #pragma unroll
            for (int mi = 0; mi < 4; mi++) {
                #pragma unroll
                for (int nj = 0; nj < 4; nj++) {
                    int col = n0h + wn + 8 * nj + t4 * 2;
                    float b0 = g_bias[col], b1 = g_bias[col + 1];
                    size_t row = m0h + wm + 16 * mi + g;
                    float2 v0 = {c[mi][nj][0] * sc + b0, c[mi][nj][1] * sc + b1};
                    *(float2*)(g_pre + row * N_CAT + col) = v0;
                    float2 v1 = {c[mi][nj][2] * sc + b0, c[mi][nj][3] * sc + b1};
                    *(float2*)(g_pre + (row + 8) * N_CAT + col) = v1;
                }
            }
        }
    }
    #undef ROWB
    #undef SPL_BYTES
    #undef HSTAGE
#endif
}

// ---------------------------------------------------------------------------
// Recurrence: one WARP per batch row, fully warp-synchronous (no smem, no
// __syncthreads). Lane l owns neurons j = 128m + 4l + q (m,q in 0..3).
// Ballot word i=4m+q (uniform across warp): bit l <-> neuron 128m+4l+q.
// ---------------------------------------------------------------------------
__global__ void __launch_bounds__(128) recur_kernel(
    const float* __restrict__ W_pc, const float* __restrict__ b_pc,
    const float* __restrict__ W_d1, const float* __restrict__ W_d2,
    const float* __restrict__ b_d2, float* __restrict__ out)
{
    const int wid  = threadIdx.x >> 5;
    const int l    = threadIdx.x & 31;
    const int r    = blockIdx.x * 4 + wid;      // batch row

    float m1[16], m2[16], m3[16];
    #pragma unroll
    for (int i = 0; i < 16; i++) { m1[i] = 0.f; m2[i] = 0.f; m3[i] = 0.f; }
    float oacc[OUT_N] = {0.f, 0.f, 0.f, 0.f, 0.f, 0.f, 0.f};

    for (int t = 0; t < T_STEPS; t++) {
        const float* pre = g_pre + ((size_t)t * B_ROWS + r) * N_CAT;
        unsigned bal[16];

        // ---- LIF1 (input = precomputed x@W_gc + b_gc) ----
        #pragma unroll
        for (int m = 0; m < 4; m++) {
            float4 p = *(const float4*)(pre + 128 * m + 4 * l);
            float pv[4] = {p.x, p.y, p.z, p.w};
            #pragma unroll
            for (int q = 0; q < 4; q++) {
                float v = 0.5f * (m1[4 * m + q] + pv[q]);
                bool  s = v > 1.0f;
                m1[4 * m + q] = s ? 0.f : v;
                bal[4 * m + q] = __ballot_sync(0xffffffffu, s);
            }
        }

        // ---- pc_pre = gc @ W_pc + b_pc (sparse row gather) ----
        float a2[16];
        #pragma unroll
        for (int m = 0; m < 4; m++) {
            float4 bv = *(const float4*)(b_pc + 128 * m + 4 * l);
            a2[4 * m + 0] = bv.x; a2[4 * m + 1] = bv.y;
            a2[4 * m + 2] = bv.z; a2[4 * m + 3] = bv.w;
        }
        #pragma unroll
        for (int mw = 0; mw < 16; mw++) {
            unsigned mm = bal[mw];
            while (mm) {
                int bit = __ffs(mm) - 1;
                mm &= mm - 1;
                int row2 = 128 * (mw >> 2) + 4 * bit + (mw & 3);
                const float* wr = W_pc + (size_t)row2 * HID;
                #pragma unroll
                for (int m = 0; m < 4; m++) {
                    float4 wv = *(const float4*)(wr + 128 * m + 4 * l);
                    a2[4 * m + 0] += wv.x; a2[4 * m + 1] += wv.y;
                    a2[4 * m + 2] += wv.z; a2[4 * m + 3] += wv.w;
                }
            }
        }

        // ---- LIF2 ----
        #pragma unroll
        for (int i = 0; i < 16; i++) {
            float v = 0.5f * (m2[i] + a2[i]);
            bool  s = v > 1.0f;
            m2[i] = s ? 0.f : v;
            bal[i] = __ballot_sync(0xffffffffu, s);
        }

        // ---- d1_pre = precomputed x-part + pc @ W_d1_bottom ----
        float a3[16];
        #pragma unroll
        for (int m = 0; m < 4; m++) {
            float4 p = *(const float4*)(pre + HID + 128 * m + 4 * l);
            a3[4 * m + 0] = p.x; a3[4 * m + 1] = p.y;
            a3[4 * m + 2] = p.z; a3[4 * m + 3] = p.w;
        }
        #pragma unroll
        for (int mw = 0; mw < 16; mw++) {
            unsigned mm = bal[mw];
            while (mm) {
                int bit = __ffs(mm) - 1;
                mm &= mm - 1;
                int row2 = HID + 128 * (mw >> 2) + 4 * bit + (mw & 3);
                const float* wr = W_d1 + (size_t)row2 * HID;
                #pragma unroll
                for (int m = 0; m < 4; m++) {
                    float4 wv = *(const float4*)(wr + 128 * m + 4 * l);
                    a3[4 * m + 0] += wv.x; a3[4 * m + 1] += wv.y;
                    a3[4 * m + 2] += wv.z; a3[4 * m + 3] += wv.w;
                }
            }
        }

        // ---- LIF3 -> readout ----
        #pragma unroll
        for (int i = 0; i < 16; i++) {
            float v = 0.5f * (m3[i] + a3[i]);
            bool  s = v > 1.0f;
            m3[i] = s ? 0.f : v;
            if (s) {
                int j = 128 * (i >> 2) + 4 * l + (i & 3);
                const float* wr = W_d2 + (size_t)j * OUT_N;
                #pragma unroll
                for (int o = 0; o < OUT_N; o++) oacc[o] += wr[o];
            }
        }
    }

    // ---- warp reduction of 7 outputs ----
    #pragma unroll
    for (int o = 0; o < OUT_N; o++) {
        float v = oacc[o];
        #pragma unroll
        for (int off = 16; off; off >>= 1) v += __shfl_down_sync(0xffffffffu, v, off);
        if (l == 0) out[(size_t)r * OUT_N + o] = v * (1.0f / (float)T_STEPS) + b_d2[o];
    }
}

// ---------------------------------------------------------------------------
extern "C" void kernel_launch(void* const* d_in, const int* in_sizes, int n_in,
                              void* d_out, int out_size)
{
    const float* x    = (const float*)d_in[0];
    const float* W_gc = (const float*)d_in[1];
    const float* b_gc = (const float*)d_in[2];
    const float* W_pc = (const float*)d_in[3];
    const float* b_pc = (const float*)d_in[4];
    const float* W_d1 = (const float*)d_in[5];
    const float* b_d1 = (const float*)d_in[6];
    const float* W_d2 = (const float*)d_in[7];
    const float* b_d2 = (const float*)d_in[8];
    float* out = (float*)d_out;
    (void)in_sizes; (void)n_in; (void)out_size;

    cudaFuncSetAttribute(gemm_kernel, cudaFuncAttributeMaxDynamicSharedMemorySize, GEMM_SMEM);

    convert_x_kernel<<<((size_t)M_TOT * K_DIM / 4) / 256, 256>>>((const float4*)x);
    convert_w_kernel<<<(N_CAT * K_DIM) / 256, 256>>>(W_gc, W_d1, b_gc, b_d1);

    dim3 grid(N_CAT / GN, M_TOT / GM);   // (4, 1024); x fastest -> A tiles reuse L2
    gemm_kernel<<<grid, 256, GEMM_SMEM>>>();

    recur_kernel<<<B_ROWS / 4, 128>>>(W_pc, b_pc, W_d1, W_d2, b_d2, out);
}